// round 13
// baseline (speedup 1.0000x reference)
#include <cuda_runtime.h>
#include <stdint.h>
#include <math.h>

// Problem constants
#define Bq 2
#define Nq 1024
#define Cc 256
#define NH 8
#define DH 32
#define FF 2048
#define HW0 35200   // 200x176
#define HW2 140800  // 400x352

// value buffer offsets (in floats), layout per level: [B, HW, 256]
#define VOFF0 0L
#define VOFF1 (2L*35200*256)
#define VOFF2 (2L*(35200+35200)*256)
#define VTOT  (2L*(35200+35200+140800)*256)

// ---------------- scratch (static device globals; no allocation) ----------------
__device__ float g_qkv[Bq*Nq*3*Cc];
__device__ float g_scores[(long)Bq*NH*Nq*Nq];   // 64 MB
__device__ float g_sa[Bq*Nq*Cc];
__device__ float g_tmp[Bq*Nq*Cc];
__device__ float g_q1[Bq*Nq*Cc];
__device__ float g_q2[Bq*Nq*Cc];
__device__ float g_off[Bq*Nq*192];
__device__ float g_aw[Bq*Nq*96];
__device__ float g_ca[Bq*Nq*Cc];
__device__ float g_ffh[Bq*Nq*FF];
__device__ float g_ffp[4L*Bq*Nq*Cc];            // FFN2 split-K partials (8 MB)
__device__ float g_values[VTOT];                // 432 MB

__device__ __forceinline__ void mma_tf32_16x8x8(float* c, const uint32_t* a, const uint32_t* b) {
    asm volatile(
        "mma.sync.aligned.m16n8k8.row.col.f32.tf32.tf32.f32 "
        "{%0,%1,%2,%3}, {%4,%5,%6,%7}, {%8,%9}, {%0,%1,%2,%3};"
        : "+f"(c[0]), "+f"(c[1]), "+f"(c[2]), "+f"(c[3])
        : "r"(a[0]), "r"(a[1]), "r"(a[2]), "r"(a[3]), "r"(b[0]), "r"(b[1]));
}

#define CP_ASYNC16(dst, src) \
    asm volatile("cp.async.cg.shared.global [%0], [%1], 16;" :: "r"(dst), "l"(src) : "memory")
#define CP_ASYNC16Z(dst, src, sz) \
    asm volatile("cp.async.cg.shared.global [%0], [%1], 16, %2;" :: "r"(dst), "l"(src), "r"(sz) : "memory")
#define CP_COMMIT() asm volatile("cp.async.commit_group;" ::: "memory")
#define CP_WAIT1()  asm volatile("cp.async.wait_group 1;" ::: "memory")
#define CP_WAIT0()  asm volatile("cp.async.wait_group 0;" ::: "memory")

// =====================================================================
// gemm_mma_at: A K-major [K=256][M] (k-stride = HW), W [N,256] row-major.
// =====================================================================

#define AT_A_WORDS (32*136)    // 4352
#define AT_B_WORDS (128*36)    // 4608
#define AT_SMEM    ((2*AT_A_WORDS + 2*AT_B_WORDS) * 4)   // 71680 bytes

__global__ __launch_bounds__(256, 2)
void gemm_mma_at(const float* __restrict__ feat, const float* __restrict__ W,
                 const float* __restrict__ bias, float* __restrict__ outp,
                 int HW, int ldo)
{
    extern __shared__ float sm[];
    float* As = sm;                    // [2][32][136]
    float* Bs = sm + 2 * AT_A_WORDS;   // [2][128][36]

    int tid  = threadIdx.x;
    int lane = tid & 31, wid = tid >> 5;
    int g = lane >> 2, tig = lane & 3;
    int wm = wid >> 2, wn = wid & 3;
    long pix0 = (long)blockIdx.x * 128;
    int  n0   = blockIdx.y * 128;
    int  bz   = blockIdx.z;

    const float* fb = feat + (long)bz * 256 * HW;
    uint32_t asb = (uint32_t)__cvta_generic_to_shared(As);
    uint32_t bsb = (uint32_t)__cvta_generic_to_shared(Bs);

    auto load_chunk = [&](int c, int buf) {
        #pragma unroll
        for (int i = 0; i < 4; i++) {
            int f4 = tid + 256 * i;
            int kl = f4 >> 5, p4 = f4 & 31;
            const float* src = fb + (long)(c * 32 + kl) * HW + pix0 + p4 * 4;
            CP_ASYNC16(asb + (uint32_t)((buf * AT_A_WORDS + kl * 136 + p4 * 4) * 4), src);
        }
        #pragma unroll
        for (int i = 0; i < 4; i++) {
            int f4 = tid + 256 * i;
            int r = f4 >> 3, q = f4 & 7;
            const float* src = W + (long)(n0 + r) * 256 + c * 32 + q * 4;
            CP_ASYNC16(bsb + (uint32_t)((buf * AT_B_WORDS + r * 36 + q * 4) * 4), src);
        }
        CP_COMMIT();
    };

    load_chunk(0, 0);
    load_chunk(1, 1);

    float acc[4][4][4];
    #pragma unroll
    for (int mt = 0; mt < 4; mt++)
        #pragma unroll
        for (int nt = 0; nt < 4; nt++)
            #pragma unroll
            for (int q = 0; q < 4; q++) acc[mt][nt][q] = 0.f;

    int mbase = wm * 64, nbw = wn * 32;

    #pragma unroll 1
    for (int c = 0; c < 8; c++) {
        if (c < 6) { CP_WAIT1(); } else { CP_WAIT0(); }
        __syncthreads();

        const uint32_t* A = (const uint32_t*)(As + (c & 1) * AT_A_WORDS);
        const uint32_t* B = (const uint32_t*)(Bs + (c & 1) * AT_B_WORDS);
        #pragma unroll
        for (int s = 0; s < 4; s++) {
            int k0 = s * 8;
            uint32_t af[4][4];
            #pragma unroll
            for (int mt = 0; mt < 4; mt++) {
                int m = mbase + mt * 16 + g;
                const uint32_t* ar  = A + (k0 + tig) * 136 + m;
                const uint32_t* ar2 = A + (k0 + tig + 4) * 136 + m;
                af[mt][0] = ar[0];  af[mt][1] = ar[8];
                af[mt][2] = ar2[0]; af[mt][3] = ar2[8];
            }
            uint32_t bf[4][2];
            #pragma unroll
            for (int nt = 0; nt < 4; nt++) {
                const uint32_t* br = B + (nbw + nt * 8 + g) * 36 + k0 + tig;
                bf[nt][0] = br[0]; bf[nt][1] = br[4];
            }
            #pragma unroll
            for (int mt = 0; mt < 4; mt++)
                #pragma unroll
                for (int nt = 0; nt < 4; nt++)
                    mma_tf32_16x8x8(acc[mt][nt], af[mt], bf[nt]);
        }
        __syncthreads();
        if (c + 2 < 8) load_chunk(c + 2, c & 1);
    }

    float* ob = outp + (long)bz * HW * ldo;
    #pragma unroll
    for (int nt = 0; nt < 4; nt++) {
        int nc = n0 + nbw + nt * 8 + tig * 2;
        float b0 = bias[nc], b1 = bias[nc + 1];
        #pragma unroll
        for (int mt = 0; mt < 4; mt++) {
            long r = pix0 + mbase + mt * 16 + g;
            float2 v0 = make_float2(acc[mt][nt][0] + b0, acc[mt][nt][1] + b1);
            float2 v1 = make_float2(acc[mt][nt][2] + b0, acc[mt][nt][3] + b1);
            *(float2*)(ob + r * ldo + nc)       = v0;
            *(float2*)(ob + (r + 8) * ldo + nc) = v1;
        }
    }
}

// =====================================================================
// gemm_mma_a: A row-major [M][lda], W row-major [Nc][K], Out [M][ldo].
// =====================================================================

#define GA_WORDS (128*36)   // per buffer: 4608 words

__global__ __launch_bounds__(256, 2)
void gemm_mma_a(const float* __restrict__ A, const float* __restrict__ W,
                const float* __restrict__ bias, float* __restrict__ Out,
                int Nc, int K, int lda, int ldo, int relu)
{
    extern __shared__ float sm[];
    float* As = sm;                 // [2][128][36]
    float* Bs = sm + 2 * GA_WORDS;  // [2][128][36]

    int tid = threadIdx.x, lane = tid & 31, wid = tid >> 5;
    int g = lane >> 2, tig = lane & 3;
    int wm = wid >> 2, wn = wid & 3;
    int m0 = blockIdx.x * 128, n0 = blockIdx.y * 128;
    int nch = K >> 5;
    uint32_t asb = (uint32_t)__cvta_generic_to_shared(As);
    uint32_t bsb = (uint32_t)__cvta_generic_to_shared(Bs);

    auto load_chunk = [&](int c, int buf) {
        #pragma unroll
        for (int i = 0; i < 4; i++) {
            int f4 = tid + 256 * i;
            int r = f4 >> 3, q = f4 & 7;
            const float* srcA = A + (long)(m0 + r) * lda + c * 32 + q * 4;
            uint32_t da = asb + (uint32_t)((buf * GA_WORDS + r * 36 + q * 4) * 4);
            CP_ASYNC16(da, srcA);
            int nrow = n0 + r;
            int ok = (nrow < Nc) ? 16 : 0;
            const float* srcB = W + (long)(ok ? nrow : 0) * K + c * 32 + q * 4;
            uint32_t db = bsb + (uint32_t)((buf * GA_WORDS + r * 36 + q * 4) * 4);
            CP_ASYNC16Z(db, srcB, ok);
        }
        CP_COMMIT();
    };

    load_chunk(0, 0);
    if (nch > 1) load_chunk(1, 1);

    float acc[4][4][4];
    #pragma unroll
    for (int mt = 0; mt < 4; mt++)
        #pragma unroll
        for (int nt = 0; nt < 4; nt++)
            #pragma unroll
            for (int q = 0; q < 4; q++) acc[mt][nt][q] = 0.f;

    int mbase = wm * 64, nbw = wn * 32;

    #pragma unroll 1
    for (int c = 0; c < nch; c++) {
        if (c < nch - 2) { CP_WAIT1(); } else { CP_WAIT0(); }
        __syncthreads();

        const uint32_t* Ab = (const uint32_t*)(As + (c & 1) * GA_WORDS);
        const uint32_t* Bb = (const uint32_t*)(Bs + (c & 1) * GA_WORDS);
        #pragma unroll
        for (int s = 0; s < 4; s++) {
            int k = s * 8 + tig;
            uint32_t af[4][4];
            #pragma unroll
            for (int mt = 0; mt < 4; mt++) {
                const uint32_t* p = Ab + (mbase + mt * 16 + g) * 36 + k;
                af[mt][0] = p[0];       af[mt][1] = p[8 * 36];
                af[mt][2] = p[4];       af[mt][3] = p[8 * 36 + 4];
            }
            uint32_t bf[4][2];
            #pragma unroll
            for (int nt = 0; nt < 4; nt++) {
                const uint32_t* p = Bb + (nbw + nt * 8 + g) * 36 + k;
                bf[nt][0] = p[0]; bf[nt][1] = p[4];
            }
            #pragma unroll
            for (int mt = 0; mt < 4; mt++)
                #pragma unroll
                for (int nt = 0; nt < 4; nt++)
                    mma_tf32_16x8x8(acc[mt][nt], af[mt], bf[nt]);
        }
        __syncthreads();
        if (c + 2 < nch) load_chunk(c + 2, c & 1);
    }

    #pragma unroll
    for (int nt = 0; nt < 4; nt++) {
        int nc = n0 + nbw + nt * 8 + tig * 2;
        if (nc < Nc) {
            float b0 = bias[nc], b1 = bias[nc + 1];
            #pragma unroll
            for (int mt = 0; mt < 4; mt++) {
                long r = m0 + mbase + mt * 16 + g;
                float v0 = acc[mt][nt][0] + b0, v1 = acc[mt][nt][1] + b1;
                float v2 = acc[mt][nt][2] + b0, v3 = acc[mt][nt][3] + b1;
                if (relu) {
                    v0 = fmaxf(v0, 0.f); v1 = fmaxf(v1, 0.f);
                    v2 = fmaxf(v2, 0.f); v3 = fmaxf(v3, 0.f);
                }
                *(float2*)(Out + r * ldo + nc)       = make_float2(v0, v1);
                *(float2*)(Out + (r + 8) * ldo + nc) = make_float2(v2, v3);
            }
        }
    }
}

// =====================================================================
// ffn2_sk: split-K FFN2. A=[2048][2048] (g_ffh), W=[256][2048].
//   blockIdx.z = K-slice s (K=512, koff=s*512); partial -> g_ffp[s].
// =====================================================================
__global__ __launch_bounds__(256, 2)
void ffn2_sk(const float* __restrict__ A, const float* __restrict__ W,
             float* __restrict__ Parts)
{
    extern __shared__ float sm[];
    float* As = sm;
    float* Bs = sm + 2 * GA_WORDS;

    int tid = threadIdx.x, lane = tid & 31, wid = tid >> 5;
    int g = lane >> 2, tig = lane & 3;
    int wm = wid >> 2, wn = wid & 3;
    int m0 = blockIdx.x * 128, n0 = blockIdx.y * 128;
    int koff = blockIdx.z * 512;
    float* Out = Parts + (long)blockIdx.z * (Bq * Nq * 256);
    uint32_t asb = (uint32_t)__cvta_generic_to_shared(As);
    uint32_t bsb = (uint32_t)__cvta_generic_to_shared(Bs);

    auto load_chunk = [&](int c, int buf) {
        #pragma unroll
        for (int i = 0; i < 4; i++) {
            int f4 = tid + 256 * i;
            int r = f4 >> 3, q = f4 & 7;
            const float* srcA = A + (long)(m0 + r) * 2048 + koff + c * 32 + q * 4;
            CP_ASYNC16(asb + (uint32_t)((buf * GA_WORDS + r * 36 + q * 4) * 4), srcA);
            const float* srcB = W + (long)(n0 + r) * 2048 + koff + c * 32 + q * 4;
            CP_ASYNC16(bsb + (uint32_t)((buf * GA_WORDS + r * 36 + q * 4) * 4), srcB);
        }
        CP_COMMIT();
    };

    load_chunk(0, 0);
    load_chunk(1, 1);

    float acc[4][4][4];
    #pragma unroll
    for (int mt = 0; mt < 4; mt++)
        #pragma unroll
        for (int nt = 0; nt < 4; nt++)
            #pragma unroll
            for (int q = 0; q < 4; q++) acc[mt][nt][q] = 0.f;

    int mbase = wm * 64, nbw = wn * 32;

    #pragma unroll 1
    for (int c = 0; c < 16; c++) {
        if (c < 14) { CP_WAIT1(); } else { CP_WAIT0(); }
        __syncthreads();
        const uint32_t* Ab = (const uint32_t*)(As + (c & 1) * GA_WORDS);
        const uint32_t* Bb = (const uint32_t*)(Bs + (c & 1) * GA_WORDS);
        #pragma unroll
        for (int s = 0; s < 4; s++) {
            int k = s * 8 + tig;
            uint32_t af[4][4];
            #pragma unroll
            for (int mt = 0; mt < 4; mt++) {
                const uint32_t* p = Ab + (mbase + mt * 16 + g) * 36 + k;
                af[mt][0] = p[0];       af[mt][1] = p[8 * 36];
                af[mt][2] = p[4];       af[mt][3] = p[8 * 36 + 4];
            }
            uint32_t bf[4][2];
            #pragma unroll
            for (int nt = 0; nt < 4; nt++) {
                const uint32_t* p = Bb + (nbw + nt * 8 + g) * 36 + k;
                bf[nt][0] = p[0]; bf[nt][1] = p[4];
            }
            #pragma unroll
            for (int mt = 0; mt < 4; mt++)
                #pragma unroll
                for (int nt = 0; nt < 4; nt++)
                    mma_tf32_16x8x8(acc[mt][nt], af[mt], bf[nt]);
        }
        __syncthreads();
        if (c + 2 < 16) load_chunk(c + 2, c & 1);
    }

    #pragma unroll
    for (int nt = 0; nt < 4; nt++) {
        int nc = n0 + nbw + nt * 8 + tig * 2;
        #pragma unroll
        for (int mt = 0; mt < 4; mt++) {
            long r = m0 + mbase + mt * 16 + g;
            *(float2*)(Out + r * 256 + nc)       = make_float2(acc[mt][nt][0], acc[mt][nt][1]);
            *(float2*)(Out + (r + 8) * 256 + nc) = make_float2(acc[mt][nt][2], acc[mt][nt][3]);
        }
    }
}

// =====================================================================
// scores_mma: per (b,h): S[128,128] tile = Q[128,32] @ K[128,32]^T * scale
// =====================================================================
__global__ __launch_bounds__(256, 2)
void scores_mma(const float* __restrict__ qkv, float* __restrict__ scores)
{
    __shared__ float Qs[128][36];
    __shared__ float Ks[128][36];
    int z = blockIdx.z, b = z >> 3, h = z & 7;
    int i0 = blockIdx.x * 128, j0 = blockIdx.y * 128;
    int tid = threadIdx.x, lane = tid & 31, wid = tid >> 5;
    int g = lane >> 2, tig = lane & 3;
    int wm = wid >> 2, wn = wid & 3;

    uint32_t qb = (uint32_t)__cvta_generic_to_shared(Qs);
    uint32_t kb = (uint32_t)__cvta_generic_to_shared(Ks);
    #pragma unroll
    for (int i = 0; i < 4; i++) {
        int f4 = tid + 256 * i;
        int r = f4 >> 3, q = f4 & 7;
        const float* sq = qkv + (long)(b * Nq + i0 + r) * 768 + h * 32 + q * 4;
        const float* sk = qkv + (long)(b * Nq + j0 + r) * 768 + 256 + h * 32 + q * 4;
        CP_ASYNC16(qb + (uint32_t)((r * 36 + q * 4) * 4), sq);
        CP_ASYNC16(kb + (uint32_t)((r * 36 + q * 4) * 4), sk);
    }
    CP_COMMIT();
    CP_WAIT0();
    __syncthreads();

    float acc[4][4][4];
    #pragma unroll
    for (int mt = 0; mt < 4; mt++)
        #pragma unroll
        for (int nt = 0; nt < 4; nt++)
            #pragma unroll
            for (int q = 0; q < 4; q++) acc[mt][nt][q] = 0.f;

    int mbase = wm * 64, nbw = wn * 32;
    const uint32_t* Qu = (const uint32_t*)Qs;
    const uint32_t* Ku = (const uint32_t*)Ks;
    #pragma unroll
    for (int s = 0; s < 4; s++) {
        int k = s * 8 + tig;
        uint32_t af[4][4];
        #pragma unroll
        for (int mt = 0; mt < 4; mt++) {
            const uint32_t* p = Qu + (mbase + mt * 16 + g) * 36 + k;
            af[mt][0] = p[0];  af[mt][1] = p[8 * 36];
            af[mt][2] = p[4];  af[mt][3] = p[8 * 36 + 4];
        }
        uint32_t bf[4][2];
        #pragma unroll
        for (int nt = 0; nt < 4; nt++) {
            const uint32_t* p = Ku + (nbw + nt * 8 + g) * 36 + k;
            bf[nt][0] = p[0]; bf[nt][1] = p[4];
        }
        #pragma unroll
        for (int mt = 0; mt < 4; mt++)
            #pragma unroll
            for (int nt = 0; nt < 4; nt++)
                mma_tf32_16x8x8(acc[mt][nt], af[mt], bf[nt]);
    }

    const float sc = 0.17677669529663689f;
    #pragma unroll
    for (int nt = 0; nt < 4; nt++) {
        int col = j0 + nbw + nt * 8 + tig * 2;
        #pragma unroll
        for (int mt = 0; mt < 4; mt++) {
            long r = (long)z * Nq + i0 + mbase + mt * 16 + g;
            *(float2*)(scores + r * Nq + col) =
                make_float2(acc[mt][nt][0] * sc, acc[mt][nt][1] * sc);
            *(float2*)(scores + (r + 8) * Nq + col) =
                make_float2(acc[mt][nt][2] * sc, acc[mt][nt][3] * sc);
        }
    }
}

// =====================================================================
// pv_mma: per (b,h): O[128,32] = P[128,1024] @ V[1024,32]
// =====================================================================
__global__ __launch_bounds__(256, 2)
void pv_mma(const float* __restrict__ scores, const float* __restrict__ qkv,
            float* __restrict__ sa)
{
    __shared__ float Ps[2][128][36];   // 36864 B
    __shared__ float Vs[2][32][40];    // 10240 B
    int z = blockIdx.y, b = z >> 3, h = z & 7;
    int i0 = blockIdx.x * 128;
    int tid = threadIdx.x, lane = tid & 31, wid = tid >> 5;
    int g = lane >> 2, tig = lane & 3;
    int mbase = wid * 16;

    const float* Pb = scores + ((long)z * Nq + i0) * Nq;
    const float* Vb = qkv + (long)b * Nq * 768 + 512 + h * 32;
    uint32_t pb = (uint32_t)__cvta_generic_to_shared(Ps);
    uint32_t vb = (uint32_t)__cvta_generic_to_shared(Vs);

    auto load_chunk = [&](int c, int buf) {
        #pragma unroll
        for (int i = 0; i < 4; i++) {
            int f4 = tid + 256 * i;
            int r = f4 >> 3, q = f4 & 7;
            const float* src = Pb + (long)r * Nq + c * 32 + q * 4;
            CP_ASYNC16(pb + (uint32_t)((buf * 128 * 36 + r * 36 + q * 4) * 4), src);
        }
        {
            int r = tid >> 3, q = tid & 7;
            const float* src = Vb + (long)(c * 32 + r) * 768 + q * 4;
            CP_ASYNC16(vb + (uint32_t)((buf * 32 * 40 + r * 40 + q * 4) * 4), src);
        }
        CP_COMMIT();
    };

    load_chunk(0, 0);
    load_chunk(1, 1);

    float acc[4][4];
    #pragma unroll
    for (int nt = 0; nt < 4; nt++)
        #pragma unroll
        for (int q = 0; q < 4; q++) acc[nt][q] = 0.f;

    #pragma unroll 1
    for (int c = 0; c < 32; c++) {
        if (c < 30) { CP_WAIT1(); } else { CP_WAIT0(); }
        __syncthreads();
        const uint32_t* Pu = (const uint32_t*)Ps[c & 1];
        const uint32_t* Vu = (const uint32_t*)Vs[c & 1];
        #pragma unroll
        for (int s = 0; s < 4; s++) {
            int k = s * 8 + tig;
            uint32_t af[4];
            const uint32_t* p = Pu + (mbase + g) * 36 + k;
            af[0] = p[0];       af[1] = p[8 * 36];
            af[2] = p[4];       af[3] = p[8 * 36 + 4];
            #pragma unroll
            for (int nt = 0; nt < 4; nt++) {
                uint32_t bf[2];
                const uint32_t* vp = Vu + k * 40 + nt * 8 + g;
                bf[0] = vp[0]; bf[1] = vp[4 * 40];
                mma_tf32_16x8x8(acc[nt], af, bf);
            }
        }
        __syncthreads();
        if (c + 2 < 32) load_chunk(c + 2, c & 1);
    }

    #pragma unroll
    for (int nt = 0; nt < 4; nt++) {
        int col = h * 32 + nt * 8 + tig * 2;
        long r = (long)b * Nq + i0 + mbase + g;
        *(float2*)(sa + r * 256 + col)       = make_float2(acc[nt][0], acc[nt][1]);
        *(float2*)(sa + (r + 8) * 256 + col) = make_float2(acc[nt][2], acc[nt][3]);
    }
}

// ---------------- softmax ----------------
__global__ void softmax_kernel(float* __restrict__ scores)
{
    long row = blockIdx.x;
    float* p = scores + row * Nq;
    int tid = threadIdx.x;
    float v[4];
    float mx = -1e30f;
    #pragma unroll
    for (int t=0;t<4;t++) { v[t] = p[tid + t*256]; mx = fmaxf(mx, v[t]); }
    __shared__ float sm[8];
    #pragma unroll
    for (int o=16;o>0;o>>=1) mx = fmaxf(mx, __shfl_xor_sync(0xffffffffu, mx, o));
    if ((tid & 31) == 0) sm[tid>>5] = mx;
    __syncthreads();
    float m2 = sm[0];
    #pragma unroll
    for (int w=1;w<8;w++) m2 = fmaxf(m2, sm[w]);
    float s = 0.f;
    #pragma unroll
    for (int t=0;t<4;t++) { v[t] = __expf(v[t]-m2); s += v[t]; }
    #pragma unroll
    for (int o=16;o>0;o>>=1) s += __shfl_xor_sync(0xffffffffu, s, o);
    __syncthreads();
    if ((tid & 31) == 0) sm[tid>>5] = s;
    __syncthreads();
    float st = 0.f;
    #pragma unroll
    for (int w=0;w<8;w++) st += sm[w];
    float inv = 1.f/st;
    #pragma unroll
    for (int t=0;t<4;t++) p[tid + t*256] = v[t]*inv;
}

// ---------------- residual + LayerNorm (optional transposed in/out) ----------------
__global__ void add_ln_kernel(const float* __restrict__ x, int x_t,
                              const float* __restrict__ y,
                              const float* __restrict__ g, const float* __restrict__ be,
                              float* __restrict__ out, int out_t)
{
    int bn = blockIdx.x, b = bn >> 10, n = bn & 1023;
    int c = threadIdx.x;
    float xv = x_t ? x[(long)(b*256 + c)*Nq + n] : x[(long)bn*256 + c];
    float v = xv + y[(long)bn*256 + c];
    __shared__ float s1[8], s2[8];
    float a = v, q = v*v;
    #pragma unroll
    for (int o=16;o>0;o>>=1) { a += __shfl_xor_sync(0xffffffffu, a, o); q += __shfl_xor_sync(0xffffffffu, q, o); }
    if ((c & 31) == 0) { s1[c>>5] = a; s2[c>>5] = q; }
    __syncthreads();
    float sa_ = 0.f, sq = 0.f;
    #pragma unroll
    for (int w=0;w<8;w++) { sa_ += s1[w]; sq += s2[w]; }
    float mean = sa_*(1.f/256.f);
    float var  = sq*(1.f/256.f) - mean*mean;
    float inv  = rsqrtf(var + 1e-5f);
    float o = (v - mean)*inv*g[c] + be[c];
    if (out_t) out[(long)(b*256 + c)*Nq + n] = o;
    else       out[(long)bn*256 + c] = o;
}

// ---------------- residual + 4-partial reduce + bias + LayerNorm (FFN2 tail) ----------------
__global__ void add_ln4_kernel(const float* __restrict__ x,
                               const float* __restrict__ parts,
                               const float* __restrict__ bias,
                               const float* __restrict__ g, const float* __restrict__ be,
                               float* __restrict__ out)
{
    int bn = blockIdx.x, b = bn >> 10, n = bn & 1023;
    int c = threadIdx.x;
    const long stride = (long)Bq * Nq * 256;
    float v = x[(long)bn*256 + c] + bias[c];
    #pragma unroll
    for (int s = 0; s < 4; s++) v += parts[s * stride + (long)bn*256 + c];
    __shared__ float s1[8], s2[8];
    float a = v, q = v*v;
    #pragma unroll
    for (int o=16;o>0;o>>=1) { a += __shfl_xor_sync(0xffffffffu, a, o); q += __shfl_xor_sync(0xffffffffu, q, o); }
    if ((c & 31) == 0) { s1[c>>5] = a; s2[c>>5] = q; }
    __syncthreads();
    float sa_ = 0.f, sq = 0.f;
    #pragma unroll
    for (int w=0;w<8;w++) { sa_ += s1[w]; sq += s2[w]; }
    float mean = sa_*(1.f/256.f);
    float var  = sq*(1.f/256.f) - mean*mean;
    float inv  = rsqrtf(var + 1e-5f);
    float o = (v - mean)*inv*g[c] + be[c];
    out[(long)(b*256 + c)*Nq + n] = o;   // transposed final output
}

// ---------------- multi-scale deformable sampling ----------------
__global__ void deform_kernel(const float* __restrict__ off, const float* __restrict__ awr,
                              const float* __restrict__ qpos, float* __restrict__ ca)
{
    int bn = blockIdx.x, b = bn >> 10;
    int tid = threadIdx.x;       // tid = h*32 + d
    int h = tid >> 5;
    __shared__ float s_off[192], s_aw[96];
    if (tid < 192) s_off[tid] = off[(long)bn*192 + tid];
    if (tid < 96)  s_aw[tid]  = awr[(long)bn*96 + tid];
    __syncthreads();

    float wl[12];
    {
        float mx = -1e30f;
        #pragma unroll
        for (int t=0;t<12;t++) mx = fmaxf(mx, s_aw[h*12+t]);
        float s = 0.f;
        #pragma unroll
        for (int t=0;t<12;t++) { wl[t] = __expf(s_aw[h*12+t]-mx); s += wl[t]; }
        float inv = 1.f/s;
        #pragma unroll
        for (int t=0;t<12;t++) wl[t] *= inv;
    }
    float rx = qpos[(long)bn*2+0] * (1.f/352.f);
    float ry = qpos[(long)bn*2+1] * (1.f/400.f);
    float acc = 0.f;
    #pragma unroll
    for (int l = 0; l < 3; l++) {
        const int Hh = (l < 2) ? 200 : 400;
        const int Ww = (l < 2) ? 176 : 352;
        const long base = ((l == 0) ? VOFF0 : (l == 1) ? VOFF1 : VOFF2)
                          + (long)b * Hh * Ww * 256 + tid;
        float fx = rx * (float)Ww, fy = ry * (float)Hh;
        #pragma unroll
        for (int p = 0; p < 4; p++) {
            int oi = (h*12 + l*4 + p)*2;
            float x = fx + s_off[oi]   - 0.5f;
            float y = fy + s_off[oi+1] - 0.5f;
            float x0f = floorf(x), y0f = floorf(y);
            float wx = x - x0f, wy = y - y0f;
            float aw = wl[l*4+p];
            float w00 = (1.f-wx)*(1.f-wy)*aw, w10 = wx*(1.f-wy)*aw;
            float w01 = (1.f-wx)*wy*aw,       w11 = wx*wy*aw;
            bool vx0 = (x0f >= 0.f)  & (x0f <  (float)Ww);
            bool vx1 = (x0f >= -1.f) & (x0f <  (float)(Ww-1));
            bool vy0 = (y0f >= 0.f)  & (y0f <  (float)Hh);
            bool vy1 = (y0f >= -1.f) & (y0f <  (float)(Hh-1));
            if (vx0 | vx1) {
                int ix0 = (int)x0f;
                if (vy0 | vy1) {
                    int iy0 = (int)y0f;
                    if (vx0 && vy0) acc += w00 * g_values[base + (long)(iy0*Ww + ix0)*256];
                    if (vx1 && vy0) acc += w10 * g_values[base + (long)(iy0*Ww + ix0 + 1)*256];
                    if (vx0 && vy1) acc += w01 * g_values[base + (long)((iy0+1)*Ww + ix0)*256];
                    if (vx1 && vy1) acc += w11 * g_values[base + (long)((iy0+1)*Ww + ix0 + 1)*256];
                }
            }
        }
    }
    ca[(long)bn*256 + tid] = acc;
}

// ---------------- launch (single stream; R9 fork/join reverted) ----------------
extern "C" void kernel_launch(void* const* d_in, const int* in_sizes, int n_in,
                              void* d_out, int out_size)
{
    const float* query = (const float*)d_in[0];
    const float* qpos  = (const float*)d_in[1];
    const float* bev   = (const float*)d_in[2];
    const float* xc4   = (const float*)d_in[3];
    const float* xc3   = (const float*)d_in[4];
    const float* in_w  = (const float*)d_in[5];
    const float* in_b  = (const float*)d_in[6];
    const float* op_w  = (const float*)d_in[7];
    const float* op_b  = (const float*)d_in[8];
    const float* w_off = (const float*)d_in[9];
    const float* b_off = (const float*)d_in[10];
    const float* w_att = (const float*)d_in[11];
    const float* b_att = (const float*)d_in[12];
    const float* w_val = (const float*)d_in[13];
    const float* b_val = (const float*)d_in[14];
    const float* w_out = (const float*)d_in[15];
    const float* b_out = (const float*)d_in[16];
    const float* w_f1  = (const float*)d_in[17];
    const float* b_f1  = (const float*)d_in[18];
    const float* w_f2  = (const float*)d_in[19];
    const float* b_f2  = (const float*)d_in[20];
    const float* g1  = (const float*)d_in[21];
    const float* be1 = (const float*)d_in[22];
    const float* g2  = (const float*)d_in[23];
    const float* be2 = (const float*)d_in[24];
    const float* g3  = (const float*)d_in[25];
    const float* be3 = (const float*)d_in[26];
    float* out = (float*)d_out;
    (void)in_sizes; (void)n_in; (void)out_size;

    float *p_qkv, *p_scores, *p_sa, *p_tmp, *p_q1, *p_q2, *p_off, *p_aw, *p_ca, *p_val, *p_ffh, *p_ffp;
    cudaGetSymbolAddress((void**)&p_qkv,    g_qkv);
    cudaGetSymbolAddress((void**)&p_scores, g_scores);
    cudaGetSymbolAddress((void**)&p_sa,     g_sa);
    cudaGetSymbolAddress((void**)&p_tmp,    g_tmp);
    cudaGetSymbolAddress((void**)&p_q1,     g_q1);
    cudaGetSymbolAddress((void**)&p_q2,     g_q2);
    cudaGetSymbolAddress((void**)&p_off,    g_off);
    cudaGetSymbolAddress((void**)&p_aw,     g_aw);
    cudaGetSymbolAddress((void**)&p_ca,     g_ca);
    cudaGetSymbolAddress((void**)&p_val,    g_values);
    cudaGetSymbolAddress((void**)&p_ffh,    g_ffh);
    cudaGetSymbolAddress((void**)&p_ffp,    g_ffp);

    cudaFuncSetAttribute(gemm_mma_at, cudaFuncAttributeMaxDynamicSharedMemorySize, AT_SMEM);
    cudaFuncSetAttribute(gemm_mma_a,  cudaFuncAttributeMaxDynamicSharedMemorySize, 4*GA_WORDS*4);
    cudaFuncSetAttribute(ffn2_sk,     cudaFuncAttributeMaxDynamicSharedMemorySize, 4*GA_WORDS*4);

    // ---- value projections (tf32 mma) ----
    gemm_mma_at<<<dim3(HW0/128, 2, 2), 256, AT_SMEM>>>(bev, w_val, b_val, p_val + VOFF0, HW0, 256);
    gemm_mma_at<<<dim3(HW0/128, 2, 2), 256, AT_SMEM>>>(xc4, w_val, b_val, p_val + VOFF1, HW0, 256);
    gemm_mma_at<<<dim3(HW2/128, 2, 2), 256, AT_SMEM>>>(xc3, w_val, b_val, p_val + VOFF2, HW2, 256);

    // ---- self-attention ----
    gemm_mma_at<<<dim3(8, 6, 2), 256, AT_SMEM>>>(query, in_w, in_b, p_qkv, 1024, 768);
    scores_mma<<<dim3(8, 8, 16), 256>>>(p_qkv, p_scores);
    softmax_kernel<<<16384, 256>>>(p_scores);
    pv_mma<<<dim3(8, 16), 256>>>(p_scores, p_qkv, p_sa);
    gemm_mma_a<<<dim3(16, 2), 256, 4*GA_WORDS*4>>>(p_sa, op_w, op_b, p_tmp, 256, 256, 256, 256, 0);
    add_ln_kernel<<<2048, 256>>>(query, 1, p_tmp, g1, be1, p_q1, 0);

    // ---- deformable cross-attention ----
    gemm_mma_a<<<dim3(16, 2), 256, 4*GA_WORDS*4>>>(p_q1, w_off, b_off, p_off, 192, 256, 256, 192, 0);
    gemm_mma_a<<<dim3(16, 1), 256, 4*GA_WORDS*4>>>(p_q1, w_att, b_att, p_aw, 96, 256, 256, 96, 0);
    deform_kernel<<<2048, 256>>>(p_off, p_aw, qpos, p_ca);
    gemm_mma_a<<<dim3(16, 2), 256, 4*GA_WORDS*4>>>(p_ca, w_out, b_out, p_tmp, 256, 256, 256, 256, 0);
    add_ln_kernel<<<2048, 256>>>(p_q1, 0, p_tmp, g2, be2, p_q2, 0);

    // ---- FFN ----
    gemm_mma_a<<<dim3(16, 16), 256, 4*GA_WORDS*4>>>(p_q2, w_f1, b_f1, p_ffh, 2048, 256, 256, 2048, 1);
    ffn2_sk<<<dim3(16, 2, 4), 256, 4*GA_WORDS*4>>>(p_ffh, w_f2, p_ffp);
    add_ln4_kernel<<<2048, 256>>>(p_q2, p_ffp, b_f2, g3, be3, out);
}

// round 14
// speedup vs baseline: 1.5622x; 1.5622x over previous
#include <cuda_runtime.h>
#include <stdint.h>
#include <math.h>

// Problem constants
#define Bq 2
#define Nq 1024
#define Cc 256
#define NH 8
#define DH 32
#define FF 2048
#define HW0 35200   // 200x176
#define HW2 140800  // 400x352

// value buffer offsets (in floats), layout per level: [B, HW, 256]
#define VOFF0 0L
#define VOFF1 (2L*35200*256)
#define VOFF2 (2L*(35200+35200)*256)
#define VTOT  (2L*(35200+35200+140800)*256)

// ---------------- scratch (static device globals; no allocation) ----------------
__device__ float g_qkv[Bq*Nq*3*Cc];
__device__ float g_sa[Bq*Nq*Cc];
__device__ float g_tmp[Bq*Nq*Cc];
__device__ float g_q1[Bq*Nq*Cc];
__device__ float g_q2[Bq*Nq*Cc];
__device__ float g_off[Bq*Nq*192];
__device__ float g_aw[Bq*Nq*96];
__device__ float g_ca[Bq*Nq*Cc];
__device__ float g_ffh[Bq*Nq*FF];
__device__ float g_ffp[4L*Bq*Nq*Cc];            // FFN2 split-K partials (8 MB)
__device__ float g_values[VTOT];                // 432 MB

__device__ __forceinline__ void mma_tf32_16x8x8(float* c, const uint32_t* a, const uint32_t* b) {
    asm volatile(
        "mma.sync.aligned.m16n8k8.row.col.f32.tf32.tf32.f32 "
        "{%0,%1,%2,%3}, {%4,%5,%6,%7}, {%8,%9}, {%0,%1,%2,%3};"
        : "+f"(c[0]), "+f"(c[1]), "+f"(c[2]), "+f"(c[3])
        : "r"(a[0]), "r"(a[1]), "r"(a[2]), "r"(a[3]), "r"(b[0]), "r"(b[1]));
}

#define CP_ASYNC16(dst, src) \
    asm volatile("cp.async.cg.shared.global [%0], [%1], 16;" :: "r"(dst), "l"(src) : "memory")
#define CP_ASYNC16Z(dst, src, sz) \
    asm volatile("cp.async.cg.shared.global [%0], [%1], 16, %2;" :: "r"(dst), "l"(src), "r"(sz) : "memory")
#define CP_COMMIT() asm volatile("cp.async.commit_group;" ::: "memory")
#define CP_WAIT1()  asm volatile("cp.async.wait_group 1;" ::: "memory")
#define CP_WAIT0()  asm volatile("cp.async.wait_group 0;" ::: "memory")

// =====================================================================
// gemm_mma_at: A K-major [K=256][M] (k-stride = HW), W [N,256] row-major.
// =====================================================================

#define AT_A_WORDS (32*136)    // 4352
#define AT_B_WORDS (128*36)    // 4608
#define AT_SMEM    ((2*AT_A_WORDS + 2*AT_B_WORDS) * 4)   // 71680 bytes

__global__ __launch_bounds__(256, 2)
void gemm_mma_at(const float* __restrict__ feat, const float* __restrict__ W,
                 const float* __restrict__ bias, float* __restrict__ outp,
                 int HW, int ldo)
{
    extern __shared__ float sm[];
    float* As = sm;                    // [2][32][136]
    float* Bs = sm + 2 * AT_A_WORDS;   // [2][128][36]

    int tid  = threadIdx.x;
    int lane = tid & 31, wid = tid >> 5;
    int g = lane >> 2, tig = lane & 3;
    int wm = wid >> 2, wn = wid & 3;
    long pix0 = (long)blockIdx.x * 128;
    int  n0   = blockIdx.y * 128;
    int  bz   = blockIdx.z;

    const float* fb = feat + (long)bz * 256 * HW;
    uint32_t asb = (uint32_t)__cvta_generic_to_shared(As);
    uint32_t bsb = (uint32_t)__cvta_generic_to_shared(Bs);

    auto load_chunk = [&](int c, int buf) {
        #pragma unroll
        for (int i = 0; i < 4; i++) {
            int f4 = tid + 256 * i;
            int kl = f4 >> 5, p4 = f4 & 31;
            const float* src = fb + (long)(c * 32 + kl) * HW + pix0 + p4 * 4;
            CP_ASYNC16(asb + (uint32_t)((buf * AT_A_WORDS + kl * 136 + p4 * 4) * 4), src);
        }
        #pragma unroll
        for (int i = 0; i < 4; i++) {
            int f4 = tid + 256 * i;
            int r = f4 >> 3, q = f4 & 7;
            const float* src = W + (long)(n0 + r) * 256 + c * 32 + q * 4;
            CP_ASYNC16(bsb + (uint32_t)((buf * AT_B_WORDS + r * 36 + q * 4) * 4), src);
        }
        CP_COMMIT();
    };

    load_chunk(0, 0);
    load_chunk(1, 1);

    float acc[4][4][4];
    #pragma unroll
    for (int mt = 0; mt < 4; mt++)
        #pragma unroll
        for (int nt = 0; nt < 4; nt++)
            #pragma unroll
            for (int q = 0; q < 4; q++) acc[mt][nt][q] = 0.f;

    int mbase = wm * 64, nbw = wn * 32;

    #pragma unroll 1
    for (int c = 0; c < 8; c++) {
        if (c < 6) { CP_WAIT1(); } else { CP_WAIT0(); }
        __syncthreads();

        const uint32_t* A = (const uint32_t*)(As + (c & 1) * AT_A_WORDS);
        const uint32_t* B = (const uint32_t*)(Bs + (c & 1) * AT_B_WORDS);
        #pragma unroll
        for (int s = 0; s < 4; s++) {
            int k0 = s * 8;
            uint32_t af[4][4];
            #pragma unroll
            for (int mt = 0; mt < 4; mt++) {
                int m = mbase + mt * 16 + g;
                const uint32_t* ar  = A + (k0 + tig) * 136 + m;
                const uint32_t* ar2 = A + (k0 + tig + 4) * 136 + m;
                af[mt][0] = ar[0];  af[mt][1] = ar[8];
                af[mt][2] = ar2[0]; af[mt][3] = ar2[8];
            }
            uint32_t bf[4][2];
            #pragma unroll
            for (int nt = 0; nt < 4; nt++) {
                const uint32_t* br = B + (nbw + nt * 8 + g) * 36 + k0 + tig;
                bf[nt][0] = br[0]; bf[nt][1] = br[4];
            }
            #pragma unroll
            for (int mt = 0; mt < 4; mt++)
                #pragma unroll
                for (int nt = 0; nt < 4; nt++)
                    mma_tf32_16x8x8(acc[mt][nt], af[mt], bf[nt]);
        }
        __syncthreads();
        if (c + 2 < 8) load_chunk(c + 2, c & 1);
    }

    float* ob = outp + (long)bz * HW * ldo;
    #pragma unroll
    for (int nt = 0; nt < 4; nt++) {
        int nc = n0 + nbw + nt * 8 + tig * 2;
        float b0 = bias[nc], b1 = bias[nc + 1];
        #pragma unroll
        for (int mt = 0; mt < 4; mt++) {
            long r = pix0 + mbase + mt * 16 + g;
            float2 v0 = make_float2(acc[mt][nt][0] + b0, acc[mt][nt][1] + b1);
            float2 v1 = make_float2(acc[mt][nt][2] + b0, acc[mt][nt][3] + b1);
            *(float2*)(ob + r * ldo + nc)       = v0;
            *(float2*)(ob + (r + 8) * ldo + nc) = v1;
        }
    }
}

// =====================================================================
// gemm_mma_a: A row-major [M][lda], W row-major [Nc][K], Out [M][ldo].
// =====================================================================

#define GA_WORDS (128*36)   // per buffer: 4608 words

__global__ __launch_bounds__(256, 2)
void gemm_mma_a(const float* __restrict__ A, const float* __restrict__ W,
                const float* __restrict__ bias, float* __restrict__ Out,
                int Nc, int K, int lda, int ldo, int relu)
{
    extern __shared__ float sm[];
    float* As = sm;                 // [2][128][36]
    float* Bs = sm + 2 * GA_WORDS;  // [2][128][36]

    int tid = threadIdx.x, lane = tid & 31, wid = tid >> 5;
    int g = lane >> 2, tig = lane & 3;
    int wm = wid >> 2, wn = wid & 3;
    int m0 = blockIdx.x * 128, n0 = blockIdx.y * 128;
    int nch = K >> 5;
    uint32_t asb = (uint32_t)__cvta_generic_to_shared(As);
    uint32_t bsb = (uint32_t)__cvta_generic_to_shared(Bs);

    auto load_chunk = [&](int c, int buf) {
        #pragma unroll
        for (int i = 0; i < 4; i++) {
            int f4 = tid + 256 * i;
            int r = f4 >> 3, q = f4 & 7;
            const float* srcA = A + (long)(m0 + r) * lda + c * 32 + q * 4;
            uint32_t da = asb + (uint32_t)((buf * GA_WORDS + r * 36 + q * 4) * 4);
            CP_ASYNC16(da, srcA);
            int nrow = n0 + r;
            int ok = (nrow < Nc) ? 16 : 0;
            const float* srcB = W + (long)(ok ? nrow : 0) * K + c * 32 + q * 4;
            uint32_t db = bsb + (uint32_t)((buf * GA_WORDS + r * 36 + q * 4) * 4);
            CP_ASYNC16Z(db, srcB, ok);
        }
        CP_COMMIT();
    };

    load_chunk(0, 0);
    if (nch > 1) load_chunk(1, 1);

    float acc[4][4][4];
    #pragma unroll
    for (int mt = 0; mt < 4; mt++)
        #pragma unroll
        for (int nt = 0; nt < 4; nt++)
            #pragma unroll
            for (int q = 0; q < 4; q++) acc[mt][nt][q] = 0.f;

    int mbase = wm * 64, nbw = wn * 32;

    #pragma unroll 1
    for (int c = 0; c < nch; c++) {
        if (c < nch - 2) { CP_WAIT1(); } else { CP_WAIT0(); }
        __syncthreads();

        const uint32_t* Ab = (const uint32_t*)(As + (c & 1) * GA_WORDS);
        const uint32_t* Bb = (const uint32_t*)(Bs + (c & 1) * GA_WORDS);
        #pragma unroll
        for (int s = 0; s < 4; s++) {
            int k = s * 8 + tig;
            uint32_t af[4][4];
            #pragma unroll
            for (int mt = 0; mt < 4; mt++) {
                const uint32_t* p = Ab + (mbase + mt * 16 + g) * 36 + k;
                af[mt][0] = p[0];       af[mt][1] = p[8 * 36];
                af[mt][2] = p[4];       af[mt][3] = p[8 * 36 + 4];
            }
            uint32_t bf[4][2];
            #pragma unroll
            for (int nt = 0; nt < 4; nt++) {
                const uint32_t* p = Bb + (nbw + nt * 8 + g) * 36 + k;
                bf[nt][0] = p[0]; bf[nt][1] = p[4];
            }
            #pragma unroll
            for (int mt = 0; mt < 4; mt++)
                #pragma unroll
                for (int nt = 0; nt < 4; nt++)
                    mma_tf32_16x8x8(acc[mt][nt], af[mt], bf[nt]);
        }
        __syncthreads();
        if (c + 2 < nch) load_chunk(c + 2, c & 1);
    }

    #pragma unroll
    for (int nt = 0; nt < 4; nt++) {
        int nc = n0 + nbw + nt * 8 + tig * 2;
        if (nc < Nc) {
            float b0 = bias[nc], b1 = bias[nc + 1];
            #pragma unroll
            for (int mt = 0; mt < 4; mt++) {
                long r = m0 + mbase + mt * 16 + g;
                float v0 = acc[mt][nt][0] + b0, v1 = acc[mt][nt][1] + b1;
                float v2 = acc[mt][nt][2] + b0, v3 = acc[mt][nt][3] + b1;
                if (relu) {
                    v0 = fmaxf(v0, 0.f); v1 = fmaxf(v1, 0.f);
                    v2 = fmaxf(v2, 0.f); v3 = fmaxf(v3, 0.f);
                }
                *(float2*)(Out + r * ldo + nc)       = make_float2(v0, v1);
                *(float2*)(Out + (r + 8) * ldo + nc) = make_float2(v2, v3);
            }
        }
    }
}

// =====================================================================
// ffn2_sk: split-K FFN2. A=[2048][2048] (g_ffh), W=[256][2048].
// =====================================================================
__global__ __launch_bounds__(256, 2)
void ffn2_sk(const float* __restrict__ A, const float* __restrict__ W,
             float* __restrict__ Parts)
{
    extern __shared__ float sm[];
    float* As = sm;
    float* Bs = sm + 2 * GA_WORDS;

    int tid = threadIdx.x, lane = tid & 31, wid = tid >> 5;
    int g = lane >> 2, tig = lane & 3;
    int wm = wid >> 2, wn = wid & 3;
    int m0 = blockIdx.x * 128, n0 = blockIdx.y * 128;
    int koff = blockIdx.z * 512;
    float* Out = Parts + (long)blockIdx.z * (Bq * Nq * 256);
    uint32_t asb = (uint32_t)__cvta_generic_to_shared(As);
    uint32_t bsb = (uint32_t)__cvta_generic_to_shared(Bs);

    auto load_chunk = [&](int c, int buf) {
        #pragma unroll
        for (int i = 0; i < 4; i++) {
            int f4 = tid + 256 * i;
            int r = f4 >> 3, q = f4 & 7;
            const float* srcA = A + (long)(m0 + r) * 2048 + koff + c * 32 + q * 4;
            CP_ASYNC16(asb + (uint32_t)((buf * GA_WORDS + r * 36 + q * 4) * 4), srcA);
            const float* srcB = W + (long)(n0 + r) * 2048 + koff + c * 32 + q * 4;
            CP_ASYNC16(bsb + (uint32_t)((buf * GA_WORDS + r * 36 + q * 4) * 4), srcB);
        }
        CP_COMMIT();
    };

    load_chunk(0, 0);
    load_chunk(1, 1);

    float acc[4][4][4];
    #pragma unroll
    for (int mt = 0; mt < 4; mt++)
        #pragma unroll
        for (int nt = 0; nt < 4; nt++)
            #pragma unroll
            for (int q = 0; q < 4; q++) acc[mt][nt][q] = 0.f;

    int mbase = wm * 64, nbw = wn * 32;

    #pragma unroll 1
    for (int c = 0; c < 16; c++) {
        if (c < 14) { CP_WAIT1(); } else { CP_WAIT0(); }
        __syncthreads();
        const uint32_t* Ab = (const uint32_t*)(As + (c & 1) * GA_WORDS);
        const uint32_t* Bb = (const uint32_t*)(Bs + (c & 1) * GA_WORDS);
        #pragma unroll
        for (int s = 0; s < 4; s++) {
            int k = s * 8 + tig;
            uint32_t af[4][4];
            #pragma unroll
            for (int mt = 0; mt < 4; mt++) {
                const uint32_t* p = Ab + (mbase + mt * 16 + g) * 36 + k;
                af[mt][0] = p[0];       af[mt][1] = p[8 * 36];
                af[mt][2] = p[4];       af[mt][3] = p[8 * 36 + 4];
            }
            uint32_t bf[4][2];
            #pragma unroll
            for (int nt = 0; nt < 4; nt++) {
                const uint32_t* p = Bb + (nbw + nt * 8 + g) * 36 + k;
                bf[nt][0] = p[0]; bf[nt][1] = p[4];
            }
            #pragma unroll
            for (int mt = 0; mt < 4; mt++)
                #pragma unroll
                for (int nt = 0; nt < 4; nt++)
                    mma_tf32_16x8x8(acc[mt][nt], af[mt], bf[nt]);
        }
        __syncthreads();
        if (c + 2 < 16) load_chunk(c + 2, c & 1);
    }

    #pragma unroll
    for (int nt = 0; nt < 4; nt++) {
        int nc = n0 + nbw + nt * 8 + tig * 2;
        #pragma unroll
        for (int mt = 0; mt < 4; mt++) {
            long r = m0 + mbase + mt * 16 + g;
            *(float2*)(Out + r * 256 + nc)       = make_float2(acc[mt][nt][0], acc[mt][nt][1]);
            *(float2*)(Out + (r + 8) * 256 + nc) = make_float2(acc[mt][nt][2], acc[mt][nt][3]);
        }
    }
}

// =====================================================================
// flash_attn: fused scores+softmax+PV per (b,h, i-tile of 128 queries).
//   grid (8 i-tiles, 16 bh), 256 threads, 1 CTA/SM.
//   Online softmax over 8 key-tiles of 128; K/V double-buffered cp.async.
// =====================================================================

#define FL_Q_OFF   0                         // [128][36]
#define FL_K_OFF   (128*36)                  // [2][128][36]
#define FL_V_OFF   (FL_K_OFF + 2*128*36)     // [2][128][40]
#define FL_S_OFF   (FL_V_OFF + 2*128*40)     // [128][132]
#define FL_M_OFF   (FL_S_OFF + 128*132)      // m_run[128]
#define FL_L_OFF   (FL_M_OFF + 128)          // l_run[128]
#define FL_C_OFF   (FL_L_OFF + 128)          // sc_row[128]
#define FL_WORDS   (FL_C_OFF + 128)
#define FL_SMEM    (FL_WORDS * 4)            // 165,888 bytes

__global__ __launch_bounds__(256, 1)
void flash_attn(const float* __restrict__ qkv, float* __restrict__ sa)
{
    extern __shared__ float sm[];
    float* Qs = sm + FL_Q_OFF;
    float* Ks = sm + FL_K_OFF;
    float* Vs = sm + FL_V_OFF;
    float* Ss = sm + FL_S_OFF;
    float* m_run = sm + FL_M_OFF;
    float* l_run = sm + FL_L_OFF;
    float* sc_row = sm + FL_C_OFF;

    int z = blockIdx.y, b = z >> 3, h = z & 7;
    int i0 = blockIdx.x * 128;
    int tid = threadIdx.x, lane = tid & 31, wid = tid >> 5;
    int g = lane >> 2, tig = lane & 3;
    int wm = wid >> 2, wn = wid & 3;         // scores partition
    int pvm = wid * 16;                      // pv partition

    uint32_t qb = (uint32_t)__cvta_generic_to_shared(Qs);
    uint32_t kb = (uint32_t)__cvta_generic_to_shared(Ks);
    uint32_t vb = (uint32_t)__cvta_generic_to_shared(Vs);

    // Q tile (one commit group)
    #pragma unroll
    for (int i = 0; i < 4; i++) {
        int f4 = tid + 256 * i;
        int r = f4 >> 3, q = f4 & 7;
        const float* sq = qkv + (long)(b * Nq + i0 + r) * 768 + h * 32 + q * 4;
        CP_ASYNC16(qb + (uint32_t)((r * 36 + q * 4) * 4), sq);
    }
    CP_COMMIT();

    auto load_kv = [&](int jt, int buf) {
        #pragma unroll
        for (int i = 0; i < 4; i++) {
            int f4 = tid + 256 * i;
            int r = f4 >> 3, q = f4 & 7;
            const float* sk = qkv + (long)(b * Nq + jt * 128 + r) * 768 + 256 + h * 32 + q * 4;
            CP_ASYNC16(kb + (uint32_t)((buf * 128 * 36 + r * 36 + q * 4) * 4), sk);
            const float* sv = qkv + (long)(b * Nq + jt * 128 + r) * 768 + 512 + h * 32 + q * 4;
            CP_ASYNC16(vb + (uint32_t)((buf * 128 * 40 + r * 40 + q * 4) * 4), sv);
        }
        CP_COMMIT();
    };
    load_kv(0, 0);

    // init stats + O acc
    if (tid < 128) { m_run[tid] = -1e30f; l_run[tid] = 0.f; }
    float acc_o[4][4];
    #pragma unroll
    for (int nt = 0; nt < 4; nt++)
        #pragma unroll
        for (int q = 0; q < 4; q++) acc_o[nt][q] = 0.f;

    const float scq = 0.17677669529663689f;  // 1/sqrt(32)
    const uint32_t* Qu = (const uint32_t*)Qs;

    #pragma unroll 1
    for (int jt = 0; jt < 8; jt++) {
        int buf = jt & 1;
        if (jt < 7) load_kv(jt + 1, buf ^ 1);
        if (jt < 7) { CP_WAIT1(); } else { CP_WAIT0(); }
        __syncthreads();

        // ---- S = Q @ K^T (scores layout) ----
        float acc_s[4][4][4];
        #pragma unroll
        for (int mt = 0; mt < 4; mt++)
            #pragma unroll
            for (int nt = 0; nt < 4; nt++)
                #pragma unroll
                for (int q = 0; q < 4; q++) acc_s[mt][nt][q] = 0.f;

        const uint32_t* Ku = (const uint32_t*)(Ks + buf * 128 * 36);
        int mbase = wm * 64, nbw = wn * 32;
        #pragma unroll
        for (int s = 0; s < 4; s++) {
            int k = s * 8 + tig;
            uint32_t af[4][4];
            #pragma unroll
            for (int mt = 0; mt < 4; mt++) {
                const uint32_t* p = Qu + (mbase + mt * 16 + g) * 36 + k;
                af[mt][0] = p[0];  af[mt][1] = p[8 * 36];
                af[mt][2] = p[4];  af[mt][3] = p[8 * 36 + 4];
            }
            uint32_t bf[4][2];
            #pragma unroll
            for (int nt = 0; nt < 4; nt++) {
                const uint32_t* p = Ku + (nbw + nt * 8 + g) * 36 + k;
                bf[nt][0] = p[0]; bf[nt][1] = p[4];
            }
            #pragma unroll
            for (int mt = 0; mt < 4; mt++)
                #pragma unroll
                for (int nt = 0; nt < 4; nt++)
                    mma_tf32_16x8x8(acc_s[mt][nt], af[mt], bf[nt]);
        }
        // stage scaled S to smem
        #pragma unroll
        for (int nt = 0; nt < 4; nt++) {
            int col = nbw + nt * 8 + tig * 2;
            #pragma unroll
            for (int mt = 0; mt < 4; mt++) {
                int r = mbase + mt * 16 + g;
                *(float2*)(Ss + r * 132 + col) =
                    make_float2(acc_s[mt][nt][0] * scq, acc_s[mt][nt][1] * scq);
                *(float2*)(Ss + (r + 8) * 132 + col) =
                    make_float2(acc_s[mt][nt][2] * scq, acc_s[mt][nt][3] * scq);
            }
        }
        __syncthreads();

        // ---- online softmax stats (2 threads per row) ----
        {
            int r = tid >> 1, half = tid & 1;
            float* srow = Ss + r * 132 + half * 64;
            float mx = -1e30f;
            #pragma unroll 8
            for (int i = 0; i < 64; i++) mx = fmaxf(mx, srow[i]);
            mx = fmaxf(mx, __shfl_xor_sync(0xffffffffu, mx, 1));
            float m_old = m_run[r];
            float m_new = fmaxf(m_old, mx);
            float s = 0.f;
            #pragma unroll 8
            for (int i = 0; i < 64; i++) {
                float e = __expf(srow[i] - m_new);
                srow[i] = e;
                s += e;
            }
            s += __shfl_xor_sync(0xffffffffu, s, 1);
            if (!half) {
                float scl = __expf(m_old - m_new);
                sc_row[r] = scl;
                l_run[r] = l_run[r] * scl + s;
                m_run[r] = m_new;
            }
        }
        __syncthreads();

        // ---- O = O*scale + P @ V (pv layout) ----
        {
            float sc0 = sc_row[pvm + g];
            float sc1 = sc_row[pvm + g + 8];
            #pragma unroll
            for (int nt = 0; nt < 4; nt++) {
                acc_o[nt][0] *= sc0; acc_o[nt][1] *= sc0;
                acc_o[nt][2] *= sc1; acc_o[nt][3] *= sc1;
            }
            const uint32_t* Pu = (const uint32_t*)Ss;
            const uint32_t* Vu = (const uint32_t*)(Vs + buf * 128 * 40);
            #pragma unroll
            for (int s = 0; s < 16; s++) {
                int k0 = s * 8;
                uint32_t af[4];
                const uint32_t* p = Pu + (pvm + g) * 132 + k0 + tig;
                af[0] = p[0];        af[1] = p[8 * 132];
                af[2] = p[4];        af[3] = p[8 * 132 + 4];
                #pragma unroll
                for (int nt = 0; nt < 4; nt++) {
                    uint32_t bf[2];
                    const uint32_t* vp = Vu + (k0 + tig) * 40 + nt * 8 + g;
                    bf[0] = vp[0]; bf[1] = vp[4 * 40];
                    mma_tf32_16x8x8(acc_o[nt], af, bf);
                }
            }
        }
        __syncthreads();
    }

    // ---- finalize: divide by l, write out ----
    float inv0 = 1.f / l_run[pvm + g];
    float inv1 = 1.f / l_run[pvm + g + 8];
    #pragma unroll
    for (int nt = 0; nt < 4; nt++) {
        int col = h * 32 + nt * 8 + tig * 2;
        long r = (long)b * Nq + i0 + pvm + g;
        *(float2*)(sa + r * 256 + col) =
            make_float2(acc_o[nt][0] * inv0, acc_o[nt][1] * inv0);
        *(float2*)(sa + (r + 8) * 256 + col) =
            make_float2(acc_o[nt][2] * inv1, acc_o[nt][3] * inv1);
    }
}

// ---------------- residual + LayerNorm (optional transposed in/out) ----------------
__global__ void add_ln_kernel(const float* __restrict__ x, int x_t,
                              const float* __restrict__ y,
                              const float* __restrict__ g, const float* __restrict__ be,
                              float* __restrict__ out, int out_t)
{
    int bn = blockIdx.x, b = bn >> 10, n = bn & 1023;
    int c = threadIdx.x;
    float xv = x_t ? x[(long)(b*256 + c)*Nq + n] : x[(long)bn*256 + c];
    float v = xv + y[(long)bn*256 + c];
    __shared__ float s1[8], s2[8];
    float a = v, q = v*v;
    #pragma unroll
    for (int o=16;o>0;o>>=1) { a += __shfl_xor_sync(0xffffffffu, a, o); q += __shfl_xor_sync(0xffffffffu, q, o); }
    if ((c & 31) == 0) { s1[c>>5] = a; s2[c>>5] = q; }
    __syncthreads();
    float sa_ = 0.f, sq = 0.f;
    #pragma unroll
    for (int w=0;w<8;w++) { sa_ += s1[w]; sq += s2[w]; }
    float mean = sa_*(1.f/256.f);
    float var  = sq*(1.f/256.f) - mean*mean;
    float inv  = rsqrtf(var + 1e-5f);
    float o = (v - mean)*inv*g[c] + be[c];
    if (out_t) out[(long)(b*256 + c)*Nq + n] = o;
    else       out[(long)bn*256 + c] = o;
}

// ---------------- residual + 4-partial reduce + bias + LayerNorm (FFN2 tail) ----------------
__global__ void add_ln4_kernel(const float* __restrict__ x,
                               const float* __restrict__ parts,
                               const float* __restrict__ bias,
                               const float* __restrict__ g, const float* __restrict__ be,
                               float* __restrict__ out)
{
    int bn = blockIdx.x, b = bn >> 10, n = bn & 1023;
    int c = threadIdx.x;
    const long stride = (long)Bq * Nq * 256;
    float v = x[(long)bn*256 + c] + bias[c];
    #pragma unroll
    for (int s = 0; s < 4; s++) v += parts[s * stride + (long)bn*256 + c];
    __shared__ float s1[8], s2[8];
    float a = v, q = v*v;
    #pragma unroll
    for (int o=16;o>0;o>>=1) { a += __shfl_xor_sync(0xffffffffu, a, o); q += __shfl_xor_sync(0xffffffffu, q, o); }
    if ((c & 31) == 0) { s1[c>>5] = a; s2[c>>5] = q; }
    __syncthreads();
    float sa_ = 0.f, sq = 0.f;
    #pragma unroll
    for (int w=0;w<8;w++) { sa_ += s1[w]; sq += s2[w]; }
    float mean = sa_*(1.f/256.f);
    float var  = sq*(1.f/256.f) - mean*mean;
    float inv  = rsqrtf(var + 1e-5f);
    float o = (v - mean)*inv*g[c] + be[c];
    out[(long)(b*256 + c)*Nq + n] = o;   // transposed final output
}

// ---------------- multi-scale deformable sampling ----------------
__global__ void deform_kernel(const float* __restrict__ off, const float* __restrict__ awr,
                              const float* __restrict__ qpos, float* __restrict__ ca)
{
    int bn = blockIdx.x, b = bn >> 10;
    int tid = threadIdx.x;       // tid = h*32 + d
    int h = tid >> 5;
    __shared__ float s_off[192], s_aw[96];
    if (tid < 192) s_off[tid] = off[(long)bn*192 + tid];
    if (tid < 96)  s_aw[tid]  = awr[(long)bn*96 + tid];
    __syncthreads();

    float wl[12];
    {
        float mx = -1e30f;
        #pragma unroll
        for (int t=0;t<12;t++) mx = fmaxf(mx, s_aw[h*12+t]);
        float s = 0.f;
        #pragma unroll
        for (int t=0;t<12;t++) { wl[t] = __expf(s_aw[h*12+t]-mx); s += wl[t]; }
        float inv = 1.f/s;
        #pragma unroll
        for (int t=0;t<12;t++) wl[t] *= inv;
    }
    float rx = qpos[(long)bn*2+0] * (1.f/352.f);
    float ry = qpos[(long)bn*2+1] * (1.f/400.f);
    float acc = 0.f;
    #pragma unroll
    for (int l = 0; l < 3; l++) {
        const int Hh = (l < 2) ? 200 : 400;
        const int Ww = (l < 2) ? 176 : 352;
        const long base = ((l == 0) ? VOFF0 : (l == 1) ? VOFF1 : VOFF2)
                          + (long)b * Hh * Ww * 256 + tid;
        float fx = rx * (float)Ww, fy = ry * (float)Hh;
        #pragma unroll
        for (int p = 0; p < 4; p++) {
            int oi = (h*12 + l*4 + p)*2;
            float x = fx + s_off[oi]   - 0.5f;
            float y = fy + s_off[oi+1] - 0.5f;
            float x0f = floorf(x), y0f = floorf(y);
            float wx = x - x0f, wy = y - y0f;
            float aw = wl[l*4+p];
            float w00 = (1.f-wx)*(1.f-wy)*aw, w10 = wx*(1.f-wy)*aw;
            float w01 = (1.f-wx)*wy*aw,       w11 = wx*wy*aw;
            bool vx0 = (x0f >= 0.f)  & (x0f <  (float)Ww);
            bool vx1 = (x0f >= -1.f) & (x0f <  (float)(Ww-1));
            bool vy0 = (y0f >= 0.f)  & (y0f <  (float)Hh);
            bool vy1 = (y0f >= -1.f) & (y0f <  (float)(Hh-1));
            if (vx0 | vx1) {
                int ix0 = (int)x0f;
                if (vy0 | vy1) {
                    int iy0 = (int)y0f;
                    if (vx0 && vy0) acc += w00 * g_values[base + (long)(iy0*Ww + ix0)*256];
                    if (vx1 && vy0) acc += w10 * g_values[base + (long)(iy0*Ww + ix0 + 1)*256];
                    if (vx0 && vy1) acc += w01 * g_values[base + (long)((iy0+1)*Ww + ix0)*256];
                    if (vx1 && vy1) acc += w11 * g_values[base + (long)((iy0+1)*Ww + ix0 + 1)*256];
                }
            }
        }
    }
    ca[(long)bn*256 + tid] = acc;
}

// ---------------- launch ----------------
extern "C" void kernel_launch(void* const* d_in, const int* in_sizes, int n_in,
                              void* d_out, int out_size)
{
    const float* query = (const float*)d_in[0];
    const float* qpos  = (const float*)d_in[1];
    const float* bev   = (const float*)d_in[2];
    const float* xc4   = (const float*)d_in[3];
    const float* xc3   = (const float*)d_in[4];
    const float* in_w  = (const float*)d_in[5];
    const float* in_b  = (const float*)d_in[6];
    const float* op_w  = (const float*)d_in[7];
    const float* op_b  = (const float*)d_in[8];
    const float* w_off = (const float*)d_in[9];
    const float* b_off = (const float*)d_in[10];
    const float* w_att = (const float*)d_in[11];
    const float* b_att = (const float*)d_in[12];
    const float* w_val = (const float*)d_in[13];
    const float* b_val = (const float*)d_in[14];
    const float* w_out = (const float*)d_in[15];
    const float* b_out = (const float*)d_in[16];
    const float* w_f1  = (const float*)d_in[17];
    const float* b_f1  = (const float*)d_in[18];
    const float* w_f2  = (const float*)d_in[19];
    const float* b_f2  = (const float*)d_in[20];
    const float* g1  = (const float*)d_in[21];
    const float* be1 = (const float*)d_in[22];
    const float* g2  = (const float*)d_in[23];
    const float* be2 = (const float*)d_in[24];
    const float* g3  = (const float*)d_in[25];
    const float* be3 = (const float*)d_in[26];
    float* out = (float*)d_out;
    (void)in_sizes; (void)n_in; (void)out_size;

    float *p_qkv, *p_sa, *p_tmp, *p_q1, *p_q2, *p_off, *p_aw, *p_ca, *p_val, *p_ffh, *p_ffp;
    cudaGetSymbolAddress((void**)&p_qkv, g_qkv);
    cudaGetSymbolAddress((void**)&p_sa,  g_sa);
    cudaGetSymbolAddress((void**)&p_tmp, g_tmp);
    cudaGetSymbolAddress((void**)&p_q1,  g_q1);
    cudaGetSymbolAddress((void**)&p_q2,  g_q2);
    cudaGetSymbolAddress((void**)&p_off, g_off);
    cudaGetSymbolAddress((void**)&p_aw,  g_aw);
    cudaGetSymbolAddress((void**)&p_ca,  g_ca);
    cudaGetSymbolAddress((void**)&p_val, g_values);
    cudaGetSymbolAddress((void**)&p_ffh, g_ffh);
    cudaGetSymbolAddress((void**)&p_ffp, g_ffp);

    cudaFuncSetAttribute(gemm_mma_at, cudaFuncAttributeMaxDynamicSharedMemorySize, AT_SMEM);
    cudaFuncSetAttribute(gemm_mma_a,  cudaFuncAttributeMaxDynamicSharedMemorySize, 4*GA_WORDS*4);
    cudaFuncSetAttribute(ffn2_sk,     cudaFuncAttributeMaxDynamicSharedMemorySize, 4*GA_WORDS*4);
    cudaFuncSetAttribute(flash_attn,  cudaFuncAttributeMaxDynamicSharedMemorySize, FL_SMEM);

    // ---- value projections (tf32 mma) ----
    gemm_mma_at<<<dim3(HW0/128, 2, 2), 256, AT_SMEM>>>(bev, w_val, b_val, p_val + VOFF0, HW0, 256);
    gemm_mma_at<<<dim3(HW0/128, 2, 2), 256, AT_SMEM>>>(xc4, w_val, b_val, p_val + VOFF1, HW0, 256);
    gemm_mma_at<<<dim3(HW2/128, 2, 2), 256, AT_SMEM>>>(xc3, w_val, b_val, p_val + VOFF2, HW2, 256);

    // ---- self-attention (fused flash) ----
    gemm_mma_at<<<dim3(8, 6, 2), 256, AT_SMEM>>>(query, in_w, in_b, p_qkv, 1024, 768);
    flash_attn<<<dim3(8, 16), 256, FL_SMEM>>>(p_qkv, p_sa);
    gemm_mma_a<<<dim3(16, 2), 256, 4*GA_WORDS*4>>>(p_sa, op_w, op_b, p_tmp, 256, 256, 256, 256, 0);
    add_ln_kernel<<<2048, 256>>>(query, 1, p_tmp, g1, be1, p_q1, 0);

    // ---- deformable cross-attention ----
    gemm_mma_a<<<dim3(16, 2), 256, 4*GA_WORDS*4>>>(p_q1, w_off, b_off, p_off, 192, 256, 256, 192, 0);
    gemm_mma_a<<<dim3(16, 1), 256, 4*GA_WORDS*4>>>(p_q1, w_att, b_att, p_aw, 96, 256, 256, 96, 0);
    deform_kernel<<<2048, 256>>>(p_off, p_aw, qpos, p_ca);
    gemm_mma_a<<<dim3(16, 2), 256, 4*GA_WORDS*4>>>(p_ca, w_out, b_out, p_tmp, 256, 256, 256, 256, 0);
    add_ln_kernel<<<2048, 256>>>(p_q1, 0, p_tmp, g2, be2, p_q2, 0);

    // ---- FFN ----
    gemm_mma_a<<<dim3(16, 16), 256, 4*GA_WORDS*4>>>(p_q2, w_f1, b_f1, p_ffh, 2048, 256, 256, 2048, 1);
    ffn2_sk<<<dim3(16, 2, 4), 256, 4*GA_WORDS*4>>>(p_ffh, w_f2, p_ffp);
    add_ln4_kernel<<<2048, 256>>>(p_q2, p_ffp, b_f2, g3, be3, out);
}

// round 15
// speedup vs baseline: 1.6044x; 1.0270x over previous
#include <cuda_runtime.h>
#include <cuda_fp16.h>
#include <stdint.h>
#include <math.h>

// Problem constants
#define Bq 2
#define Nq 1024
#define Cc 256
#define NH 8
#define DH 32
#define FF 2048
#define HW0 35200   // 200x176
#define HW2 140800  // 400x352

// value buffer offsets (in halfs), layout per level: [B, HW, 256]
#define VOFF0 0L
#define VOFF1 (2L*35200*256)
#define VOFF2 (2L*(35200+35200)*256)
#define VTOT  (2L*(35200+35200+140800)*256)

// ---------------- scratch (static device globals; no allocation) ----------------
__device__ float g_qkv[Bq*Nq*3*Cc];
__device__ float g_sa[Bq*Nq*Cc];
__device__ float g_tmp[Bq*Nq*Cc];
__device__ float g_q1[Bq*Nq*Cc];
__device__ float g_q2[Bq*Nq*Cc];
__device__ float g_off[Bq*Nq*192];
__device__ float g_aw[Bq*Nq*96];
__device__ float g_ca[Bq*Nq*Cc];
__device__ float g_ffh[Bq*Nq*FF];
__device__ float g_ffp[4L*Bq*Nq*Cc];            // FFN2 split-K partials (8 MB)
__device__ __half g_values[VTOT];               // 216 MB (fp16 values)

__device__ __forceinline__ void mma_tf32_16x8x8(float* c, const uint32_t* a, const uint32_t* b) {
    asm volatile(
        "mma.sync.aligned.m16n8k8.row.col.f32.tf32.tf32.f32 "
        "{%0,%1,%2,%3}, {%4,%5,%6,%7}, {%8,%9}, {%0,%1,%2,%3};"
        : "+f"(c[0]), "+f"(c[1]), "+f"(c[2]), "+f"(c[3])
        : "r"(a[0]), "r"(a[1]), "r"(a[2]), "r"(a[3]), "r"(b[0]), "r"(b[1]));
}

#define CP_ASYNC16(dst, src) \
    asm volatile("cp.async.cg.shared.global [%0], [%1], 16;" :: "r"(dst), "l"(src) : "memory")
#define CP_ASYNC16Z(dst, src, sz) \
    asm volatile("cp.async.cg.shared.global [%0], [%1], 16, %2;" :: "r"(dst), "l"(src), "r"(sz) : "memory")
#define CP_COMMIT() asm volatile("cp.async.commit_group;" ::: "memory")
#define CP_WAIT1()  asm volatile("cp.async.wait_group 1;" ::: "memory")
#define CP_WAIT0()  asm volatile("cp.async.wait_group 0;" ::: "memory")

// =====================================================================
// gemm_mma_at: A K-major [K=256][M] (k-stride = HW), W [N,256] row-major.
//   half_out=1 -> write __half into outp, else float.
// =====================================================================

#define AT_A_WORDS (32*136)    // 4352
#define AT_B_WORDS (128*36)    // 4608
#define AT_SMEM    ((2*AT_A_WORDS + 2*AT_B_WORDS) * 4)   // 71680 bytes

__global__ __launch_bounds__(256, 2)
void gemm_mma_at(const float* __restrict__ feat, const float* __restrict__ W,
                 const float* __restrict__ bias, void* __restrict__ outp,
                 int HW, int ldo, int half_out)
{
    extern __shared__ float sm[];
    float* As = sm;                    // [2][32][136]
    float* Bs = sm + 2 * AT_A_WORDS;   // [2][128][36]

    int tid  = threadIdx.x;
    int lane = tid & 31, wid = tid >> 5;
    int g = lane >> 2, tig = lane & 3;
    int wm = wid >> 2, wn = wid & 3;
    long pix0 = (long)blockIdx.x * 128;
    int  n0   = blockIdx.y * 128;
    int  bz   = blockIdx.z;

    const float* fb = feat + (long)bz * 256 * HW;
    uint32_t asb = (uint32_t)__cvta_generic_to_shared(As);
    uint32_t bsb = (uint32_t)__cvta_generic_to_shared(Bs);

    auto load_chunk = [&](int c, int buf) {
        #pragma unroll
        for (int i = 0; i < 4; i++) {
            int f4 = tid + 256 * i;
            int kl = f4 >> 5, p4 = f4 & 31;
            const float* src = fb + (long)(c * 32 + kl) * HW + pix0 + p4 * 4;
            CP_ASYNC16(asb + (uint32_t)((buf * AT_A_WORDS + kl * 136 + p4 * 4) * 4), src);
        }
        #pragma unroll
        for (int i = 0; i < 4; i++) {
            int f4 = tid + 256 * i;
            int r = f4 >> 3, q = f4 & 7;
            const float* src = W + (long)(n0 + r) * 256 + c * 32 + q * 4;
            CP_ASYNC16(bsb + (uint32_t)((buf * AT_B_WORDS + r * 36 + q * 4) * 4), src);
        }
        CP_COMMIT();
    };

    load_chunk(0, 0);
    load_chunk(1, 1);

    float acc[4][4][4];
    #pragma unroll
    for (int mt = 0; mt < 4; mt++)
        #pragma unroll
        for (int nt = 0; nt < 4; nt++)
            #pragma unroll
            for (int q = 0; q < 4; q++) acc[mt][nt][q] = 0.f;

    int mbase = wm * 64, nbw = wn * 32;

    #pragma unroll 1
    for (int c = 0; c < 8; c++) {
        if (c < 6) { CP_WAIT1(); } else { CP_WAIT0(); }
        __syncthreads();

        const uint32_t* A = (const uint32_t*)(As + (c & 1) * AT_A_WORDS);
        const uint32_t* B = (const uint32_t*)(Bs + (c & 1) * AT_B_WORDS);
        #pragma unroll
        for (int s = 0; s < 4; s++) {
            int k0 = s * 8;
            uint32_t af[4][4];
            #pragma unroll
            for (int mt = 0; mt < 4; mt++) {
                int m = mbase + mt * 16 + g;
                const uint32_t* ar  = A + (k0 + tig) * 136 + m;
                const uint32_t* ar2 = A + (k0 + tig + 4) * 136 + m;
                af[mt][0] = ar[0];  af[mt][1] = ar[8];
                af[mt][2] = ar2[0]; af[mt][3] = ar2[8];
            }
            uint32_t bf[4][2];
            #pragma unroll
            for (int nt = 0; nt < 4; nt++) {
                const uint32_t* br = B + (nbw + nt * 8 + g) * 36 + k0 + tig;
                bf[nt][0] = br[0]; bf[nt][1] = br[4];
            }
            #pragma unroll
            for (int mt = 0; mt < 4; mt++)
                #pragma unroll
                for (int nt = 0; nt < 4; nt++)
                    mma_tf32_16x8x8(acc[mt][nt], af[mt], bf[nt]);
        }
        __syncthreads();
        if (c + 2 < 8) load_chunk(c + 2, c & 1);
    }

    #pragma unroll
    for (int nt = 0; nt < 4; nt++) {
        int nc = n0 + nbw + nt * 8 + tig * 2;
        float b0 = bias[nc], b1 = bias[nc + 1];
        #pragma unroll
        for (int mt = 0; mt < 4; mt++) {
            long r = pix0 + mbase + mt * 16 + g;
            float v00 = acc[mt][nt][0] + b0, v01 = acc[mt][nt][1] + b1;
            float v10 = acc[mt][nt][2] + b0, v11 = acc[mt][nt][3] + b1;
            if (half_out) {
                __half* ob = (__half*)outp + (long)bz * HW * ldo;
                *(__half2*)(ob + r * ldo + nc)       = __floats2half2_rn(v00, v01);
                *(__half2*)(ob + (r + 8) * ldo + nc) = __floats2half2_rn(v10, v11);
            } else {
                float* ob = (float*)outp + (long)bz * HW * ldo;
                *(float2*)(ob + r * ldo + nc)       = make_float2(v00, v01);
                *(float2*)(ob + (r + 8) * ldo + nc) = make_float2(v10, v11);
            }
        }
    }
}

// =====================================================================
// gemm_body: shared 128x128 GEMM body. A row-major [M][lda], W [Nc][K].
// =====================================================================

#define GA_WORDS (128*36)   // per buffer: 4608 words

__device__ __forceinline__
void gemm_body(const float* __restrict__ A, const float* __restrict__ W,
               const float* __restrict__ bias, float* __restrict__ Out,
               int Nc, int K, int lda, int ldo, int relu,
               int m0, int n0, float* sm)
{
    float* As = sm;                 // [2][128][36]
    float* Bs = sm + 2 * GA_WORDS;  // [2][128][36]

    int tid = threadIdx.x, lane = tid & 31, wid = tid >> 5;
    int g = lane >> 2, tig = lane & 3;
    int wm = wid >> 2, wn = wid & 3;
    int nch = K >> 5;
    uint32_t asb = (uint32_t)__cvta_generic_to_shared(As);
    uint32_t bsb = (uint32_t)__cvta_generic_to_shared(Bs);

    auto load_chunk = [&](int c, int buf) {
        #pragma unroll
        for (int i = 0; i < 4; i++) {
            int f4 = tid + 256 * i;
            int r = f4 >> 3, q = f4 & 7;
            const float* srcA = A + (long)(m0 + r) * lda + c * 32 + q * 4;
            uint32_t da = asb + (uint32_t)((buf * GA_WORDS + r * 36 + q * 4) * 4);
            CP_ASYNC16(da, srcA);
            int nrow = n0 + r;
            int ok = (nrow < Nc) ? 16 : 0;
            const float* srcB = W + (long)(ok ? nrow : 0) * K + c * 32 + q * 4;
            uint32_t db = bsb + (uint32_t)((buf * GA_WORDS + r * 36 + q * 4) * 4);
            CP_ASYNC16Z(db, srcB, ok);
        }
        CP_COMMIT();
    };

    load_chunk(0, 0);
    if (nch > 1) load_chunk(1, 1);

    float acc[4][4][4];
    #pragma unroll
    for (int mt = 0; mt < 4; mt++)
        #pragma unroll
        for (int nt = 0; nt < 4; nt++)
            #pragma unroll
            for (int q = 0; q < 4; q++) acc[mt][nt][q] = 0.f;

    int mbase = wm * 64, nbw = wn * 32;

    #pragma unroll 1
    for (int c = 0; c < nch; c++) {
        if (c < nch - 2) { CP_WAIT1(); } else { CP_WAIT0(); }
        __syncthreads();

        const uint32_t* Ab = (const uint32_t*)(As + (c & 1) * GA_WORDS);
        const uint32_t* Bb = (const uint32_t*)(Bs + (c & 1) * GA_WORDS);
        #pragma unroll
        for (int s = 0; s < 4; s++) {
            int k = s * 8 + tig;
            uint32_t af[4][4];
            #pragma unroll
            for (int mt = 0; mt < 4; mt++) {
                const uint32_t* p = Ab + (mbase + mt * 16 + g) * 36 + k;
                af[mt][0] = p[0];       af[mt][1] = p[8 * 36];
                af[mt][2] = p[4];       af[mt][3] = p[8 * 36 + 4];
            }
            uint32_t bf[4][2];
            #pragma unroll
            for (int nt = 0; nt < 4; nt++) {
                const uint32_t* p = Bb + (nbw + nt * 8 + g) * 36 + k;
                bf[nt][0] = p[0]; bf[nt][1] = p[4];
            }
            #pragma unroll
            for (int mt = 0; mt < 4; mt++)
                #pragma unroll
                for (int nt = 0; nt < 4; nt++)
                    mma_tf32_16x8x8(acc[mt][nt], af[mt], bf[nt]);
        }
        __syncthreads();
        if (c + 2 < nch) load_chunk(c + 2, c & 1);
    }

    #pragma unroll
    for (int nt = 0; nt < 4; nt++) {
        int nc = n0 + nbw + nt * 8 + tig * 2;
        if (nc < Nc) {
            float b0 = bias[nc], b1 = bias[nc + 1];
            #pragma unroll
            for (int mt = 0; mt < 4; mt++) {
                long r = m0 + mbase + mt * 16 + g;
                float v0 = acc[mt][nt][0] + b0, v1 = acc[mt][nt][1] + b1;
                float v2 = acc[mt][nt][2] + b0, v3 = acc[mt][nt][3] + b1;
                if (relu) {
                    v0 = fmaxf(v0, 0.f); v1 = fmaxf(v1, 0.f);
                    v2 = fmaxf(v2, 0.f); v3 = fmaxf(v3, 0.f);
                }
                *(float2*)(Out + r * ldo + nc)       = make_float2(v0, v1);
                *(float2*)(Out + (r + 8) * ldo + nc) = make_float2(v2, v3);
            }
        }
    }
}

__global__ __launch_bounds__(256, 2)
void gemm_mma_a(const float* __restrict__ A, const float* __restrict__ W,
                const float* __restrict__ bias, float* __restrict__ Out,
                int Nc, int K, int lda, int ldo, int relu)
{
    extern __shared__ float sm[];
    gemm_body(A, W, bias, Out, Nc, K, lda, ldo, relu,
              blockIdx.x * 128, blockIdx.y * 128, sm);
}

// fused offsets + attention-weights projection: grid (16, 3)
__global__ __launch_bounds__(256, 2)
void gemm_offaw(const float* __restrict__ A,
                const float* __restrict__ w_off, const float* __restrict__ b_off,
                float* __restrict__ off_out,
                const float* __restrict__ w_att, const float* __restrict__ b_att,
                float* __restrict__ aw_out)
{
    extern __shared__ float sm[];
    int y = blockIdx.y;
    if (y < 2)
        gemm_body(A, w_off, b_off, off_out, 192, 256, 256, 192, 0,
                  blockIdx.x * 128, y * 128, sm);
    else
        gemm_body(A, w_att, b_att, aw_out, 96, 256, 256, 96, 0,
                  blockIdx.x * 128, 0, sm);
}

// =====================================================================
// ffn2_sk: split-K FFN2. A=[2048][2048] (g_ffh), W=[256][2048].
// =====================================================================
__global__ __launch_bounds__(256, 2)
void ffn2_sk(const float* __restrict__ A, const float* __restrict__ W,
             float* __restrict__ Parts)
{
    extern __shared__ float sm[];
    float* As = sm;
    float* Bs = sm + 2 * GA_WORDS;

    int tid = threadIdx.x, lane = tid & 31, wid = tid >> 5;
    int g = lane >> 2, tig = lane & 3;
    int wm = wid >> 2, wn = wid & 3;
    int m0 = blockIdx.x * 128, n0 = blockIdx.y * 128;
    int koff = blockIdx.z * 512;
    float* Out = Parts + (long)blockIdx.z * (Bq * Nq * 256);
    uint32_t asb = (uint32_t)__cvta_generic_to_shared(As);
    uint32_t bsb = (uint32_t)__cvta_generic_to_shared(Bs);

    auto load_chunk = [&](int c, int buf) {
        #pragma unroll
        for (int i = 0; i < 4; i++) {
            int f4 = tid + 256 * i;
            int r = f4 >> 3, q = f4 & 7;
            const float* srcA = A + (long)(m0 + r) * 2048 + koff + c * 32 + q * 4;
            CP_ASYNC16(asb + (uint32_t)((buf * GA_WORDS + r * 36 + q * 4) * 4), srcA);
            const float* srcB = W + (long)(n0 + r) * 2048 + koff + c * 32 + q * 4;
            CP_ASYNC16(bsb + (uint32_t)((buf * GA_WORDS + r * 36 + q * 4) * 4), srcB);
        }
        CP_COMMIT();
    };

    load_chunk(0, 0);
    load_chunk(1, 1);

    float acc[4][4][4];
    #pragma unroll
    for (int mt = 0; mt < 4; mt++)
        #pragma unroll
        for (int nt = 0; nt < 4; nt++)
            #pragma unroll
            for (int q = 0; q < 4; q++) acc[mt][nt][q] = 0.f;

    int mbase = wm * 64, nbw = wn * 32;

    #pragma unroll 1
    for (int c = 0; c < 16; c++) {
        if (c < 14) { CP_WAIT1(); } else { CP_WAIT0(); }
        __syncthreads();
        const uint32_t* Ab = (const uint32_t*)(As + (c & 1) * GA_WORDS);
        const uint32_t* Bb = (const uint32_t*)(Bs + (c & 1) * GA_WORDS);
        #pragma unroll
        for (int s = 0; s < 4; s++) {
            int k = s * 8 + tig;
            uint32_t af[4][4];
            #pragma unroll
            for (int mt = 0; mt < 4; mt++) {
                const uint32_t* p = Ab + (mbase + mt * 16 + g) * 36 + k;
                af[mt][0] = p[0];       af[mt][1] = p[8 * 36];
                af[mt][2] = p[4];       af[mt][3] = p[8 * 36 + 4];
            }
            uint32_t bf[4][2];
            #pragma unroll
            for (int nt = 0; nt < 4; nt++) {
                const uint32_t* p = Bb + (nbw + nt * 8 + g) * 36 + k;
                bf[nt][0] = p[0]; bf[nt][1] = p[4];
            }
            #pragma unroll
            for (int mt = 0; mt < 4; mt++)
                #pragma unroll
                for (int nt = 0; nt < 4; nt++)
                    mma_tf32_16x8x8(acc[mt][nt], af[mt], bf[nt]);
        }
        __syncthreads();
        if (c + 2 < 16) load_chunk(c + 2, c & 1);
    }

    #pragma unroll
    for (int nt = 0; nt < 4; nt++) {
        int nc = n0 + nbw + nt * 8 + tig * 2;
        #pragma unroll
        for (int mt = 0; mt < 4; mt++) {
            long r = m0 + mbase + mt * 16 + g;
            *(float2*)(Out + r * 256 + nc)       = make_float2(acc[mt][nt][0], acc[mt][nt][1]);
            *(float2*)(Out + (r + 8) * 256 + nc) = make_float2(acc[mt][nt][2], acc[mt][nt][3]);
        }
    }
}

// =====================================================================
// flash_attn: fused scores+softmax+PV per (b,h, i-tile of 128 queries).
// =====================================================================

#define FL_Q_OFF   0                         // [128][36]
#define FL_K_OFF   (128*36)                  // [2][128][36]
#define FL_V_OFF   (FL_K_OFF + 2*128*36)     // [2][128][40]
#define FL_S_OFF   (FL_V_OFF + 2*128*40)     // [128][132]
#define FL_M_OFF   (FL_S_OFF + 128*132)      // m_run[128]
#define FL_L_OFF   (FL_M_OFF + 128)          // l_run[128]
#define FL_C_OFF   (FL_L_OFF + 128)          // sc_row[128]
#define FL_WORDS   (FL_C_OFF + 128)
#define FL_SMEM    (FL_WORDS * 4)            // 165,888 bytes

__global__ __launch_bounds__(256, 1)
void flash_attn(const float* __restrict__ qkv, float* __restrict__ sa)
{
    extern __shared__ float sm[];
    float* Qs = sm + FL_Q_OFF;
    float* Ks = sm + FL_K_OFF;
    float* Vs = sm + FL_V_OFF;
    float* Ss = sm + FL_S_OFF;
    float* m_run = sm + FL_M_OFF;
    float* l_run = sm + FL_L_OFF;
    float* sc_row = sm + FL_C_OFF;

    int z = blockIdx.y, b = z >> 3, h = z & 7;
    int i0 = blockIdx.x * 128;
    int tid = threadIdx.x, lane = tid & 31, wid = tid >> 5;
    int g = lane >> 2, tig = lane & 3;
    int wm = wid >> 2, wn = wid & 3;         // scores partition
    int pvm = wid * 16;                      // pv partition

    uint32_t qb = (uint32_t)__cvta_generic_to_shared(Qs);
    uint32_t kb = (uint32_t)__cvta_generic_to_shared(Ks);
    uint32_t vb = (uint32_t)__cvta_generic_to_shared(Vs);

    #pragma unroll
    for (int i = 0; i < 4; i++) {
        int f4 = tid + 256 * i;
        int r = f4 >> 3, q = f4 & 7;
        const float* sq = qkv + (long)(b * Nq + i0 + r) * 768 + h * 32 + q * 4;
        CP_ASYNC16(qb + (uint32_t)((r * 36 + q * 4) * 4), sq);
    }
    CP_COMMIT();

    auto load_kv = [&](int jt, int buf) {
        #pragma unroll
        for (int i = 0; i < 4; i++) {
            int f4 = tid + 256 * i;
            int r = f4 >> 3, q = f4 & 7;
            const float* sk = qkv + (long)(b * Nq + jt * 128 + r) * 768 + 256 + h * 32 + q * 4;
            CP_ASYNC16(kb + (uint32_t)((buf * 128 * 36 + r * 36 + q * 4) * 4), sk);
            const float* sv = qkv + (long)(b * Nq + jt * 128 + r) * 768 + 512 + h * 32 + q * 4;
            CP_ASYNC16(vb + (uint32_t)((buf * 128 * 40 + r * 40 + q * 4) * 4), sv);
        }
        CP_COMMIT();
    };
    load_kv(0, 0);

    if (tid < 128) { m_run[tid] = -1e30f; l_run[tid] = 0.f; }
    float acc_o[4][4];
    #pragma unroll
    for (int nt = 0; nt < 4; nt++)
        #pragma unroll
        for (int q = 0; q < 4; q++) acc_o[nt][q] = 0.f;

    const float scq = 0.17677669529663689f;  // 1/sqrt(32)
    const uint32_t* Qu = (const uint32_t*)Qs;

    #pragma unroll 1
    for (int jt = 0; jt < 8; jt++) {
        int buf = jt & 1;
        if (jt < 7) load_kv(jt + 1, buf ^ 1);
        if (jt < 7) { CP_WAIT1(); } else { CP_WAIT0(); }
        __syncthreads();

        // ---- S = Q @ K^T ----
        float acc_s[4][4][4];
        #pragma unroll
        for (int mt = 0; mt < 4; mt++)
            #pragma unroll
            for (int nt = 0; nt < 4; nt++)
                #pragma unroll
                for (int q = 0; q < 4; q++) acc_s[mt][nt][q] = 0.f;

        const uint32_t* Ku = (const uint32_t*)(Ks + buf * 128 * 36);
        int mbase = wm * 64, nbw = wn * 32;
        #pragma unroll
        for (int s = 0; s < 4; s++) {
            int k = s * 8 + tig;
            uint32_t af[4][4];
            #pragma unroll
            for (int mt = 0; mt < 4; mt++) {
                const uint32_t* p = Qu + (mbase + mt * 16 + g) * 36 + k;
                af[mt][0] = p[0];  af[mt][1] = p[8 * 36];
                af[mt][2] = p[4];  af[mt][3] = p[8 * 36 + 4];
            }
            uint32_t bf[4][2];
            #pragma unroll
            for (int nt = 0; nt < 4; nt++) {
                const uint32_t* p = Ku + (nbw + nt * 8 + g) * 36 + k;
                bf[nt][0] = p[0]; bf[nt][1] = p[4];
            }
            #pragma unroll
            for (int mt = 0; mt < 4; mt++)
                #pragma unroll
                for (int nt = 0; nt < 4; nt++)
                    mma_tf32_16x8x8(acc_s[mt][nt], af[mt], bf[nt]);
        }
        #pragma unroll
        for (int nt = 0; nt < 4; nt++) {
            int col = nbw + nt * 8 + tig * 2;
            #pragma unroll
            for (int mt = 0; mt < 4; mt++) {
                int r = mbase + mt * 16 + g;
                *(float2*)(Ss + r * 132 + col) =
                    make_float2(acc_s[mt][nt][0] * scq, acc_s[mt][nt][1] * scq);
                *(float2*)(Ss + (r + 8) * 132 + col) =
                    make_float2(acc_s[mt][nt][2] * scq, acc_s[mt][nt][3] * scq);
            }
        }
        __syncthreads();

        // ---- online softmax stats (2 threads per row) ----
        {
            int r = tid >> 1, half = tid & 1;
            float* srow = Ss + r * 132 + half * 64;
            float mx = -1e30f;
            #pragma unroll 8
            for (int i = 0; i < 64; i++) mx = fmaxf(mx, srow[i]);
            mx = fmaxf(mx, __shfl_xor_sync(0xffffffffu, mx, 1));
            float m_old = m_run[r];
            float m_new = fmaxf(m_old, mx);
            float s = 0.f;
            #pragma unroll 8
            for (int i = 0; i < 64; i++) {
                float e = __expf(srow[i] - m_new);
                srow[i] = e;
                s += e;
            }
            s += __shfl_xor_sync(0xffffffffu, s, 1);
            if (!half) {
                float scl = __expf(m_old - m_new);
                sc_row[r] = scl;
                l_run[r] = l_run[r] * scl + s;
                m_run[r] = m_new;
            }
        }
        __syncthreads();

        // ---- O = O*scale + P @ V ----
        {
            float sc0 = sc_row[pvm + g];
            float sc1 = sc_row[pvm + g + 8];
            #pragma unroll
            for (int nt = 0; nt < 4; nt++) {
                acc_o[nt][0] *= sc0; acc_o[nt][1] *= sc0;
                acc_o[nt][2] *= sc1; acc_o[nt][3] *= sc1;
            }
            const uint32_t* Pu = (const uint32_t*)Ss;
            const uint32_t* Vu = (const uint32_t*)(Vs + buf * 128 * 40);
            #pragma unroll
            for (int s = 0; s < 16; s++) {
                int k0 = s * 8;
                uint32_t af[4];
                const uint32_t* p = Pu + (pvm + g) * 132 + k0 + tig;
                af[0] = p[0];        af[1] = p[8 * 132];
                af[2] = p[4];        af[3] = p[8 * 132 + 4];
                #pragma unroll
                for (int nt = 0; nt < 4; nt++) {
                    uint32_t bf[2];
                    const uint32_t* vp = Vu + (k0 + tig) * 40 + nt * 8 + g;
                    bf[0] = vp[0]; bf[1] = vp[4 * 40];
                    mma_tf32_16x8x8(acc_o[nt], af, bf);
                }
            }
        }
        __syncthreads();
    }

    float inv0 = 1.f / l_run[pvm + g];
    float inv1 = 1.f / l_run[pvm + g + 8];
    #pragma unroll
    for (int nt = 0; nt < 4; nt++) {
        int col = h * 32 + nt * 8 + tig * 2;
        long r = (long)b * Nq + i0 + pvm + g;
        *(float2*)(sa + r * 256 + col) =
            make_float2(acc_o[nt][0] * inv0, acc_o[nt][1] * inv0);
        *(float2*)(sa + (r + 8) * 256 + col) =
            make_float2(acc_o[nt][2] * inv1, acc_o[nt][3] * inv1);
    }
}

// ---------------- residual + LayerNorm (optional transposed in/out) ----------------
__global__ void add_ln_kernel(const float* __restrict__ x, int x_t,
                              const float* __restrict__ y,
                              const float* __restrict__ g, const float* __restrict__ be,
                              float* __restrict__ out, int out_t)
{
    int bn = blockIdx.x, b = bn >> 10, n = bn & 1023;
    int c = threadIdx.x;
    float xv = x_t ? x[(long)(b*256 + c)*Nq + n] : x[(long)bn*256 + c];
    float v = xv + y[(long)bn*256 + c];
    __shared__ float s1[8], s2[8];
    float a = v, q = v*v;
    #pragma unroll
    for (int o=16;o>0;o>>=1) { a += __shfl_xor_sync(0xffffffffu, a, o); q += __shfl_xor_sync(0xffffffffu, q, o); }
    if ((c & 31) == 0) { s1[c>>5] = a; s2[c>>5] = q; }
    __syncthreads();
    float sa_ = 0.f, sq = 0.f;
    #pragma unroll
    for (int w=0;w<8;w++) { sa_ += s1[w]; sq += s2[w]; }
    float mean = sa_*(1.f/256.f);
    float var  = sq*(1.f/256.f) - mean*mean;
    float inv  = rsqrtf(var + 1e-5f);
    float o = (v - mean)*inv*g[c] + be[c];
    if (out_t) out[(long)(b*256 + c)*Nq + n] = o;
    else       out[(long)bn*256 + c] = o;
}

// ---------------- residual + 4-partial reduce + bias + LayerNorm (FFN2 tail) ----------------
__global__ void add_ln4_kernel(const float* __restrict__ x,
                               const float* __restrict__ parts,
                               const float* __restrict__ bias,
                               const float* __restrict__ g, const float* __restrict__ be,
                               float* __restrict__ out)
{
    int bn = blockIdx.x, b = bn >> 10, n = bn & 1023;
    int c = threadIdx.x;
    const long stride = (long)Bq * Nq * 256;
    float v = x[(long)bn*256 + c] + bias[c];
    #pragma unroll
    for (int s = 0; s < 4; s++) v += parts[s * stride + (long)bn*256 + c];
    __shared__ float s1[8], s2[8];
    float a = v, q = v*v;
    #pragma unroll
    for (int o=16;o>0;o>>=1) { a += __shfl_xor_sync(0xffffffffu, a, o); q += __shfl_xor_sync(0xffffffffu, q, o); }
    if ((c & 31) == 0) { s1[c>>5] = a; s2[c>>5] = q; }
    __syncthreads();
    float sa_ = 0.f, sq = 0.f;
    #pragma unroll
    for (int w=0;w<8;w++) { sa_ += s1[w]; sq += s2[w]; }
    float mean = sa_*(1.f/256.f);
    float var  = sq*(1.f/256.f) - mean*mean;
    float inv  = rsqrtf(var + 1e-5f);
    float o = (v - mean)*inv*g[c] + be[c];
    out[(long)(b*256 + c)*Nq + n] = o;   // transposed final output
}

// ---------------- multi-scale deformable sampling (fp16 values) ----------------
__global__ void deform_kernel(const float* __restrict__ off, const float* __restrict__ awr,
                              const float* __restrict__ qpos, float* __restrict__ ca)
{
    int bn = blockIdx.x, b = bn >> 10;
    int tid = threadIdx.x;       // tid = h*32 + d
    int h = tid >> 5;
    __shared__ float s_off[192], s_aw[96];
    if (tid < 192) s_off[tid] = off[(long)bn*192 + tid];
    if (tid < 96)  s_aw[tid]  = awr[(long)bn*96 + tid];
    __syncthreads();

    float wl[12];
    {
        float mx = -1e30f;
        #pragma unroll
        for (int t=0;t<12;t++) mx = fmaxf(mx, s_aw[h*12+t]);
        float s = 0.f;
        #pragma unroll
        for (int t=0;t<12;t++) { wl[t] = __expf(s_aw[h*12+t]-mx); s += wl[t]; }
        float inv = 1.f/s;
        #pragma unroll
        for (int t=0;t<12;t++) wl[t] *= inv;
    }
    float rx = qpos[(long)bn*2+0] * (1.f/352.f);
    float ry = qpos[(long)bn*2+1] * (1.f/400.f);
    float acc = 0.f;
    #pragma unroll
    for (int l = 0; l < 3; l++) {
        const int Hh = (l < 2) ? 200 : 400;
        const int Ww = (l < 2) ? 176 : 352;
        const long base = ((l == 0) ? VOFF0 : (l == 1) ? VOFF1 : VOFF2)
                          + (long)b * Hh * Ww * 256 + tid;
        float fx = rx * (float)Ww, fy = ry * (float)Hh;
        #pragma unroll
        for (int p = 0; p < 4; p++) {
            int oi = (h*12 + l*4 + p)*2;
            float x = fx + s_off[oi]   - 0.5f;
            float y = fy + s_off[oi+1] - 0.5f;
            float x0f = floorf(x), y0f = floorf(y);
            float wx = x - x0f, wy = y - y0f;
            float aw = wl[l*4+p];
            float w00 = (1.f-wx)*(1.f-wy)*aw, w10 = wx*(1.f-wy)*aw;
            float w01 = (1.f-wx)*wy*aw,       w11 = wx*wy*aw;
            bool vx0 = (x0f >= 0.f)  & (x0f <  (float)Ww);
            bool vx1 = (x0f >= -1.f) & (x0f <  (float)(Ww-1));
            bool vy0 = (y0f >= 0.f)  & (y0f <  (float)Hh);
            bool vy1 = (y0f >= -1.f) & (y0f <  (float)(Hh-1));
            if (vx0 | vx1) {
                int ix0 = (int)x0f;
                if (vy0 | vy1) {
                    int iy0 = (int)y0f;
                    if (vx0 && vy0) acc += w00 * __half2float(g_values[base + (long)(iy0*Ww + ix0)*256]);
                    if (vx1 && vy0) acc += w10 * __half2float(g_values[base + (long)(iy0*Ww + ix0 + 1)*256]);
                    if (vx0 && vy1) acc += w01 * __half2float(g_values[base + (long)((iy0+1)*Ww + ix0)*256]);
                    if (vx1 && vy1) acc += w11 * __half2float(g_values[base + (long)((iy0+1)*Ww + ix0 + 1)*256]);
                }
            }
        }
    }
    ca[(long)bn*256 + tid] = acc;
}

// ---------------- launch ----------------
extern "C" void kernel_launch(void* const* d_in, const int* in_sizes, int n_in,
                              void* d_out, int out_size)
{
    const float* query = (const float*)d_in[0];
    const float* qpos  = (const float*)d_in[1];
    const float* bev   = (const float*)d_in[2];
    const float* xc4   = (const float*)d_in[3];
    const float* xc3   = (const float*)d_in[4];
    const float* in_w  = (const float*)d_in[5];
    const float* in_b  = (const float*)d_in[6];
    const float* op_w  = (const float*)d_in[7];
    const float* op_b  = (const float*)d_in[8];
    const float* w_off = (const float*)d_in[9];
    const float* b_off = (const float*)d_in[10];
    const float* w_att = (const float*)d_in[11];
    const float* b_att = (const float*)d_in[12];
    const float* w_val = (const float*)d_in[13];
    const float* b_val = (const float*)d_in[14];
    const float* w_out = (const float*)d_in[15];
    const float* b_out = (const float*)d_in[16];
    const float* w_f1  = (const float*)d_in[17];
    const float* b_f1  = (const float*)d_in[18];
    const float* w_f2  = (const float*)d_in[19];
    const float* b_f2  = (const float*)d_in[20];
    const float* g1  = (const float*)d_in[21];
    const float* be1 = (const float*)d_in[22];
    const float* g2  = (const float*)d_in[23];
    const float* be2 = (const float*)d_in[24];
    const float* g3  = (const float*)d_in[25];
    const float* be3 = (const float*)d_in[26];
    float* out = (float*)d_out;
    (void)in_sizes; (void)n_in; (void)out_size;

    float *p_qkv, *p_sa, *p_tmp, *p_q1, *p_q2, *p_off, *p_aw, *p_ca, *p_ffh, *p_ffp;
    __half *p_val;
    cudaGetSymbolAddress((void**)&p_qkv, g_qkv);
    cudaGetSymbolAddress((void**)&p_sa,  g_sa);
    cudaGetSymbolAddress((void**)&p_tmp, g_tmp);
    cudaGetSymbolAddress((void**)&p_q1,  g_q1);
    cudaGetSymbolAddress((void**)&p_q2,  g_q2);
    cudaGetSymbolAddress((void**)&p_off, g_off);
    cudaGetSymbolAddress((void**)&p_aw,  g_aw);
    cudaGetSymbolAddress((void**)&p_ca,  g_ca);
    cudaGetSymbolAddress((void**)&p_val, g_values);
    cudaGetSymbolAddress((void**)&p_ffh, g_ffh);
    cudaGetSymbolAddress((void**)&p_ffp, g_ffp);

    cudaFuncSetAttribute(gemm_mma_at, cudaFuncAttributeMaxDynamicSharedMemorySize, AT_SMEM);
    cudaFuncSetAttribute(gemm_mma_a,  cudaFuncAttributeMaxDynamicSharedMemorySize, 4*GA_WORDS*4);
    cudaFuncSetAttribute(gemm_offaw,  cudaFuncAttributeMaxDynamicSharedMemorySize, 4*GA_WORDS*4);
    cudaFuncSetAttribute(ffn2_sk,     cudaFuncAttributeMaxDynamicSharedMemorySize, 4*GA_WORDS*4);
    cudaFuncSetAttribute(flash_attn,  cudaFuncAttributeMaxDynamicSharedMemorySize, FL_SMEM);

    // ---- value projections (tf32 mma, fp16 output) ----
    gemm_mma_at<<<dim3(HW0/128, 2, 2), 256, AT_SMEM>>>(bev, w_val, b_val, p_val + VOFF0, HW0, 256, 1);
    gemm_mma_at<<<dim3(HW0/128, 2, 2), 256, AT_SMEM>>>(xc4, w_val, b_val, p_val + VOFF1, HW0, 256, 1);
    gemm_mma_at<<<dim3(HW2/128, 2, 2), 256, AT_SMEM>>>(xc3, w_val, b_val, p_val + VOFF2, HW2, 256, 1);

    // ---- self-attention (fused flash) ----
    gemm_mma_at<<<dim3(8, 6, 2), 256, AT_SMEM>>>(query, in_w, in_b, p_qkv, 1024, 768, 0);
    flash_attn<<<dim3(8, 16), 256, FL_SMEM>>>(p_qkv, p_sa);
    gemm_mma_a<<<dim3(16, 2), 256, 4*GA_WORDS*4>>>(p_sa, op_w, op_b, p_tmp, 256, 256, 256, 256, 0);
    add_ln_kernel<<<2048, 256>>>(query, 1, p_tmp, g1, be1, p_q1, 0);

    // ---- deformable cross-attention ----
    gemm_offaw<<<dim3(16, 3), 256, 4*GA_WORDS*4>>>(p_q1, w_off, b_off, p_off, w_att, b_att, p_aw);
    deform_kernel<<<2048, 256>>>(p_off, p_aw, qpos, p_ca);
    gemm_mma_a<<<dim3(16, 2), 256, 4*GA_WORDS*4>>>(p_ca, w_out, b_out, p_tmp, 256, 256, 256, 256, 0);
    add_ln_kernel<<<2048, 256>>>(p_q1, 0, p_tmp, g2, be2, p_q2, 0);

    // ---- FFN ----
    gemm_mma_a<<<dim3(16, 16), 256, 4*GA_WORDS*4>>>(p_q2, w_f1, b_f1, p_ffh, 2048, 256, 256, 2048, 1);
    ffn2_sk<<<dim3(16, 2, 4), 256, 4*GA_WORDS*4>>>(p_ffh, w_f2, p_ffp);
    add_ln4_kernel<<<2048, 256>>>(p_q2, p_ffp, b_f2, g3, be3, out);
}

// round 16
// speedup vs baseline: 1.7019x; 1.0607x over previous
#include <cuda_runtime.h>
#include <cuda_fp16.h>
#include <stdint.h>
#include <math.h>

// Problem constants
#define Bq 2
#define Nq 1024
#define Cc 256
#define NH 8
#define DH 32
#define FF 2048
#define HW0 35200   // 200x176
#define HW2 140800  // 400x352

// value buffer offsets (in halfs), layout per level: [B, HW, 256]
#define VOFF0 0L
#define VOFF1 (2L*35200*256)
#define VOFF2 (2L*(35200+35200)*256)
#define VTOT  (2L*(35200+35200+140800)*256)

// ---------------- scratch (static device globals; no allocation) ----------------
__device__ float g_qkv[Bq*Nq*3*Cc];
__device__ float g_sa[Bq*Nq*Cc];
__device__ float g_tmp[Bq*Nq*Cc];
__device__ float g_q1[Bq*Nq*Cc];
__device__ float g_q2[Bq*Nq*Cc];
__device__ float g_off[Bq*Nq*192];
__device__ float g_aw[Bq*Nq*96];
__device__ float g_ca[Bq*Nq*Cc];
__device__ float g_ffh[Bq*Nq*FF];
__device__ float g_ffp[4L*Bq*Nq*Cc];            // FFN2 split-K partials (8 MB)
__device__ __half g_values[VTOT];               // 216 MB (fp16 values)

__device__ __forceinline__ void mma_tf32_16x8x8(float* c, const uint32_t* a, const uint32_t* b) {
    asm volatile(
        "mma.sync.aligned.m16n8k8.row.col.f32.tf32.tf32.f32 "
        "{%0,%1,%2,%3}, {%4,%5,%6,%7}, {%8,%9}, {%0,%1,%2,%3};"
        : "+f"(c[0]), "+f"(c[1]), "+f"(c[2]), "+f"(c[3])
        : "r"(a[0]), "r"(a[1]), "r"(a[2]), "r"(a[3]), "r"(b[0]), "r"(b[1]));
}

#define CP_ASYNC16(dst, src) \
    asm volatile("cp.async.cg.shared.global [%0], [%1], 16;" :: "r"(dst), "l"(src) : "memory")
#define CP_ASYNC16Z(dst, src, sz) \
    asm volatile("cp.async.cg.shared.global [%0], [%1], 16, %2;" :: "r"(dst), "l"(src), "r"(sz) : "memory")
#define CP_COMMIT() asm volatile("cp.async.commit_group;" ::: "memory")
#define CP_WAIT1()  asm volatile("cp.async.wait_group 1;" ::: "memory")
#define CP_WAIT0()  asm volatile("cp.async.wait_group 0;" ::: "memory")

// =====================================================================
// gemm_mma_at: A K-major [K=256][M] (k-stride = HW), W [N,256] row-major.
//   half_out=1 -> write __half into outp, else float.
// =====================================================================

#define AT_A_WORDS (32*136)    // 4352
#define AT_B_WORDS (128*36)    // 4608
#define AT_SMEM    ((2*AT_A_WORDS + 2*AT_B_WORDS) * 4)   // 71680 bytes

__global__ __launch_bounds__(256, 2)
void gemm_mma_at(const float* __restrict__ feat, const float* __restrict__ W,
                 const float* __restrict__ bias, void* __restrict__ outp,
                 int HW, int ldo, int half_out)
{
    extern __shared__ float sm[];
    float* As = sm;                    // [2][32][136]
    float* Bs = sm + 2 * AT_A_WORDS;   // [2][128][36]

    int tid  = threadIdx.x;
    int lane = tid & 31, wid = tid >> 5;
    int g = lane >> 2, tig = lane & 3;
    int wm = wid >> 2, wn = wid & 3;
    long pix0 = (long)blockIdx.x * 128;
    int  n0   = blockIdx.y * 128;
    int  bz   = blockIdx.z;

    const float* fb = feat + (long)bz * 256 * HW;
    uint32_t asb = (uint32_t)__cvta_generic_to_shared(As);
    uint32_t bsb = (uint32_t)__cvta_generic_to_shared(Bs);

    auto load_chunk = [&](int c, int buf) {
        #pragma unroll
        for (int i = 0; i < 4; i++) {
            int f4 = tid + 256 * i;
            int kl = f4 >> 5, p4 = f4 & 31;
            const float* src = fb + (long)(c * 32 + kl) * HW + pix0 + p4 * 4;
            CP_ASYNC16(asb + (uint32_t)((buf * AT_A_WORDS + kl * 136 + p4 * 4) * 4), src);
        }
        #pragma unroll
        for (int i = 0; i < 4; i++) {
            int f4 = tid + 256 * i;
            int r = f4 >> 3, q = f4 & 7;
            const float* src = W + (long)(n0 + r) * 256 + c * 32 + q * 4;
            CP_ASYNC16(bsb + (uint32_t)((buf * AT_B_WORDS + r * 36 + q * 4) * 4), src);
        }
        CP_COMMIT();
    };

    load_chunk(0, 0);
    load_chunk(1, 1);

    float acc[4][4][4];
    #pragma unroll
    for (int mt = 0; mt < 4; mt++)
        #pragma unroll
        for (int nt = 0; nt < 4; nt++)
            #pragma unroll
            for (int q = 0; q < 4; q++) acc[mt][nt][q] = 0.f;

    int mbase = wm * 64, nbw = wn * 32;

    #pragma unroll 1
    for (int c = 0; c < 8; c++) {
        if (c < 6) { CP_WAIT1(); } else { CP_WAIT0(); }
        __syncthreads();

        const uint32_t* A = (const uint32_t*)(As + (c & 1) * AT_A_WORDS);
        const uint32_t* B = (const uint32_t*)(Bs + (c & 1) * AT_B_WORDS);
        #pragma unroll
        for (int s = 0; s < 4; s++) {
            int k0 = s * 8;
            uint32_t af[4][4];
            #pragma unroll
            for (int mt = 0; mt < 4; mt++) {
                int m = mbase + mt * 16 + g;
                const uint32_t* ar  = A + (k0 + tig) * 136 + m;
                const uint32_t* ar2 = A + (k0 + tig + 4) * 136 + m;
                af[mt][0] = ar[0];  af[mt][1] = ar[8];
                af[mt][2] = ar2[0]; af[mt][3] = ar2[8];
            }
            uint32_t bf[4][2];
            #pragma unroll
            for (int nt = 0; nt < 4; nt++) {
                const uint32_t* br = B + (nbw + nt * 8 + g) * 36 + k0 + tig;
                bf[nt][0] = br[0]; bf[nt][1] = br[4];
            }
            #pragma unroll
            for (int mt = 0; mt < 4; mt++)
                #pragma unroll
                for (int nt = 0; nt < 4; nt++)
                    mma_tf32_16x8x8(acc[mt][nt], af[mt], bf[nt]);
        }
        __syncthreads();
        if (c + 2 < 8) load_chunk(c + 2, c & 1);
    }

    #pragma unroll
    for (int nt = 0; nt < 4; nt++) {
        int nc = n0 + nbw + nt * 8 + tig * 2;
        float b0 = bias[nc], b1 = bias[nc + 1];
        #pragma unroll
        for (int mt = 0; mt < 4; mt++) {
            long r = pix0 + mbase + mt * 16 + g;
            float v00 = acc[mt][nt][0] + b0, v01 = acc[mt][nt][1] + b1;
            float v10 = acc[mt][nt][2] + b0, v11 = acc[mt][nt][3] + b1;
            if (half_out) {
                __half* ob = (__half*)outp + (long)bz * HW * ldo;
                *(__half2*)(ob + r * ldo + nc)       = __floats2half2_rn(v00, v01);
                *(__half2*)(ob + (r + 8) * ldo + nc) = __floats2half2_rn(v10, v11);
            } else {
                float* ob = (float*)outp + (long)bz * HW * ldo;
                *(float2*)(ob + r * ldo + nc)       = make_float2(v00, v01);
                *(float2*)(ob + (r + 8) * ldo + nc) = make_float2(v10, v11);
            }
        }
    }
}

// =====================================================================
// gemm_body: shared 128x128 GEMM body. A row-major [M][lda], W [Nc][K].
// =====================================================================

#define GA_WORDS (128*36)   // per buffer: 4608 words

__device__ __forceinline__
void gemm_body(const float* __restrict__ A, const float* __restrict__ W,
               const float* __restrict__ bias, float* __restrict__ Out,
               int Nc, int K, int lda, int ldo, int relu,
               int m0, int n0, float* sm)
{
    float* As = sm;                 // [2][128][36]
    float* Bs = sm + 2 * GA_WORDS;  // [2][128][36]

    int tid = threadIdx.x, lane = tid & 31, wid = tid >> 5;
    int g = lane >> 2, tig = lane & 3;
    int wm = wid >> 2, wn = wid & 3;
    int nch = K >> 5;
    uint32_t asb = (uint32_t)__cvta_generic_to_shared(As);
    uint32_t bsb = (uint32_t)__cvta_generic_to_shared(Bs);

    auto load_chunk = [&](int c, int buf) {
        #pragma unroll
        for (int i = 0; i < 4; i++) {
            int f4 = tid + 256 * i;
            int r = f4 >> 3, q = f4 & 7;
            const float* srcA = A + (long)(m0 + r) * lda + c * 32 + q * 4;
            uint32_t da = asb + (uint32_t)((buf * GA_WORDS + r * 36 + q * 4) * 4);
            CP_ASYNC16(da, srcA);
            int nrow = n0 + r;
            int ok = (nrow < Nc) ? 16 : 0;
            const float* srcB = W + (long)(ok ? nrow : 0) * K + c * 32 + q * 4;
            uint32_t db = bsb + (uint32_t)((buf * GA_WORDS + r * 36 + q * 4) * 4);
            CP_ASYNC16Z(db, srcB, ok);
        }
        CP_COMMIT();
    };

    load_chunk(0, 0);
    if (nch > 1) load_chunk(1, 1);

    float acc[4][4][4];
    #pragma unroll
    for (int mt = 0; mt < 4; mt++)
        #pragma unroll
        for (int nt = 0; nt < 4; nt++)
            #pragma unroll
            for (int q = 0; q < 4; q++) acc[mt][nt][q] = 0.f;

    int mbase = wm * 64, nbw = wn * 32;

    #pragma unroll 1
    for (int c = 0; c < nch; c++) {
        if (c < nch - 2) { CP_WAIT1(); } else { CP_WAIT0(); }
        __syncthreads();

        const uint32_t* Ab = (const uint32_t*)(As + (c & 1) * GA_WORDS);
        const uint32_t* Bb = (const uint32_t*)(Bs + (c & 1) * GA_WORDS);
        #pragma unroll
        for (int s = 0; s < 4; s++) {
            int k = s * 8 + tig;
            uint32_t af[4][4];
            #pragma unroll
            for (int mt = 0; mt < 4; mt++) {
                const uint32_t* p = Ab + (mbase + mt * 16 + g) * 36 + k;
                af[mt][0] = p[0];       af[mt][1] = p[8 * 36];
                af[mt][2] = p[4];       af[mt][3] = p[8 * 36 + 4];
            }
            uint32_t bf[4][2];
            #pragma unroll
            for (int nt = 0; nt < 4; nt++) {
                const uint32_t* p = Bb + (nbw + nt * 8 + g) * 36 + k;
                bf[nt][0] = p[0]; bf[nt][1] = p[4];
            }
            #pragma unroll
            for (int mt = 0; mt < 4; mt++)
                #pragma unroll
                for (int nt = 0; nt < 4; nt++)
                    mma_tf32_16x8x8(acc[mt][nt], af[mt], bf[nt]);
        }
        __syncthreads();
        if (c + 2 < nch) load_chunk(c + 2, c & 1);
    }

    #pragma unroll
    for (int nt = 0; nt < 4; nt++) {
        int nc = n0 + nbw + nt * 8 + tig * 2;
        if (nc < Nc) {
            float b0 = bias[nc], b1 = bias[nc + 1];
            #pragma unroll
            for (int mt = 0; mt < 4; mt++) {
                long r = m0 + mbase + mt * 16 + g;
                float v0 = acc[mt][nt][0] + b0, v1 = acc[mt][nt][1] + b1;
                float v2 = acc[mt][nt][2] + b0, v3 = acc[mt][nt][3] + b1;
                if (relu) {
                    v0 = fmaxf(v0, 0.f); v1 = fmaxf(v1, 0.f);
                    v2 = fmaxf(v2, 0.f); v3 = fmaxf(v3, 0.f);
                }
                *(float2*)(Out + r * ldo + nc)       = make_float2(v0, v1);
                *(float2*)(Out + (r + 8) * ldo + nc) = make_float2(v2, v3);
            }
        }
    }
}

__global__ __launch_bounds__(256, 2)
void gemm_mma_a(const float* __restrict__ A, const float* __restrict__ W,
                const float* __restrict__ bias, float* __restrict__ Out,
                int Nc, int K, int lda, int ldo, int relu)
{
    extern __shared__ float sm[];
    gemm_body(A, W, bias, Out, Nc, K, lda, ldo, relu,
              blockIdx.x * 128, blockIdx.y * 128, sm);
}

// fused offsets + attention-weights projection: grid (16, 3)
__global__ __launch_bounds__(256, 2)
void gemm_offaw(const float* __restrict__ A,
                const float* __restrict__ w_off, const float* __restrict__ b_off,
                float* __restrict__ off_out,
                const float* __restrict__ w_att, const float* __restrict__ b_att,
                float* __restrict__ aw_out)
{
    extern __shared__ float sm[];
    int y = blockIdx.y;
    if (y < 2)
        gemm_body(A, w_off, b_off, off_out, 192, 256, 256, 192, 0,
                  blockIdx.x * 128, y * 128, sm);
    else
        gemm_body(A, w_att, b_att, aw_out, 96, 256, 256, 96, 0,
                  blockIdx.x * 128, 0, sm);
}

// =====================================================================
// ffn2_sk: split-K FFN2. A=[2048][2048] (g_ffh), W=[256][2048].
// =====================================================================
__global__ __launch_bounds__(256, 2)
void ffn2_sk(const float* __restrict__ A, const float* __restrict__ W,
             float* __restrict__ Parts)
{
    extern __shared__ float sm[];
    float* As = sm;
    float* Bs = sm + 2 * GA_WORDS;

    int tid = threadIdx.x, lane = tid & 31, wid = tid >> 5;
    int g = lane >> 2, tig = lane & 3;
    int wm = wid >> 2, wn = wid & 3;
    int m0 = blockIdx.x * 128, n0 = blockIdx.y * 128;
    int koff = blockIdx.z * 512;
    float* Out = Parts + (long)blockIdx.z * (Bq * Nq * 256);
    uint32_t asb = (uint32_t)__cvta_generic_to_shared(As);
    uint32_t bsb = (uint32_t)__cvta_generic_to_shared(Bs);

    auto load_chunk = [&](int c, int buf) {
        #pragma unroll
        for (int i = 0; i < 4; i++) {
            int f4 = tid + 256 * i;
            int r = f4 >> 3, q = f4 & 7;
            const float* srcA = A + (long)(m0 + r) * 2048 + koff + c * 32 + q * 4;
            CP_ASYNC16(asb + (uint32_t)((buf * GA_WORDS + r * 36 + q * 4) * 4), srcA);
            const float* srcB = W + (long)(n0 + r) * 2048 + koff + c * 32 + q * 4;
            CP_ASYNC16(bsb + (uint32_t)((buf * GA_WORDS + r * 36 + q * 4) * 4), srcB);
        }
        CP_COMMIT();
    };

    load_chunk(0, 0);
    load_chunk(1, 1);

    float acc[4][4][4];
    #pragma unroll
    for (int mt = 0; mt < 4; mt++)
        #pragma unroll
        for (int nt = 0; nt < 4; nt++)
            #pragma unroll
            for (int q = 0; q < 4; q++) acc[mt][nt][q] = 0.f;

    int mbase = wm * 64, nbw = wn * 32;

    #pragma unroll 1
    for (int c = 0; c < 16; c++) {
        if (c < 14) { CP_WAIT1(); } else { CP_WAIT0(); }
        __syncthreads();
        const uint32_t* Ab = (const uint32_t*)(As + (c & 1) * GA_WORDS);
        const uint32_t* Bb = (const uint32_t*)(Bs + (c & 1) * GA_WORDS);
        #pragma unroll
        for (int s = 0; s < 4; s++) {
            int k = s * 8 + tig;
            uint32_t af[4][4];
            #pragma unroll
            for (int mt = 0; mt < 4; mt++) {
                const uint32_t* p = Ab + (mbase + mt * 16 + g) * 36 + k;
                af[mt][0] = p[0];       af[mt][1] = p[8 * 36];
                af[mt][2] = p[4];       af[mt][3] = p[8 * 36 + 4];
            }
            uint32_t bf[4][2];
            #pragma unroll
            for (int nt = 0; nt < 4; nt++) {
                const uint32_t* p = Bb + (nbw + nt * 8 + g) * 36 + k;
                bf[nt][0] = p[0]; bf[nt][1] = p[4];
            }
            #pragma unroll
            for (int mt = 0; mt < 4; mt++)
                #pragma unroll
                for (int nt = 0; nt < 4; nt++)
                    mma_tf32_16x8x8(acc[mt][nt], af[mt], bf[nt]);
        }
        __syncthreads();
        if (c + 2 < 16) load_chunk(c + 2, c & 1);
    }

    #pragma unroll
    for (int nt = 0; nt < 4; nt++) {
        int nc = n0 + nbw + nt * 8 + tig * 2;
        #pragma unroll
        for (int mt = 0; mt < 4; mt++) {
            long r = m0 + mbase + mt * 16 + g;
            *(float2*)(Out + r * 256 + nc)       = make_float2(acc[mt][nt][0], acc[mt][nt][1]);
            *(float2*)(Out + (r + 8) * 256 + nc) = make_float2(acc[mt][nt][2], acc[mt][nt][3]);
        }
    }
}

// =====================================================================
// flash_attn: fused scores+softmax+PV per (b,h, i-tile of 128 queries).
// =====================================================================

#define FL_Q_OFF   0                         // [128][36]
#define FL_K_OFF   (128*36)                  // [2][128][36]
#define FL_V_OFF   (FL_K_OFF + 2*128*36)     // [2][128][40]
#define FL_S_OFF   (FL_V_OFF + 2*128*40)     // [128][132]
#define FL_M_OFF   (FL_S_OFF + 128*132)      // m_run[128]
#define FL_L_OFF   (FL_M_OFF + 128)          // l_run[128]
#define FL_C_OFF   (FL_L_OFF + 128)          // sc_row[128]
#define FL_WORDS   (FL_C_OFF + 128)
#define FL_SMEM    (FL_WORDS * 4)            // 165,888 bytes

__global__ __launch_bounds__(256, 1)
void flash_attn(const float* __restrict__ qkv, float* __restrict__ sa)
{
    extern __shared__ float sm[];
    float* Qs = sm + FL_Q_OFF;
    float* Ks = sm + FL_K_OFF;
    float* Vs = sm + FL_V_OFF;
    float* Ss = sm + FL_S_OFF;
    float* m_run = sm + FL_M_OFF;
    float* l_run = sm + FL_L_OFF;
    float* sc_row = sm + FL_C_OFF;

    int z = blockIdx.y, b = z >> 3, h = z & 7;
    int i0 = blockIdx.x * 128;
    int tid = threadIdx.x, lane = tid & 31, wid = tid >> 5;
    int g = lane >> 2, tig = lane & 3;
    int wm = wid >> 2, wn = wid & 3;         // scores partition
    int pvm = wid * 16;                      // pv partition

    uint32_t qb = (uint32_t)__cvta_generic_to_shared(Qs);
    uint32_t kb = (uint32_t)__cvta_generic_to_shared(Ks);
    uint32_t vb = (uint32_t)__cvta_generic_to_shared(Vs);

    #pragma unroll
    for (int i = 0; i < 4; i++) {
        int f4 = tid + 256 * i;
        int r = f4 >> 3, q = f4 & 7;
        const float* sq = qkv + (long)(b * Nq + i0 + r) * 768 + h * 32 + q * 4;
        CP_ASYNC16(qb + (uint32_t)((r * 36 + q * 4) * 4), sq);
    }
    CP_COMMIT();

    auto load_kv = [&](int jt, int buf) {
        #pragma unroll
        for (int i = 0; i < 4; i++) {
            int f4 = tid + 256 * i;
            int r = f4 >> 3, q = f4 & 7;
            const float* sk = qkv + (long)(b * Nq + jt * 128 + r) * 768 + 256 + h * 32 + q * 4;
            CP_ASYNC16(kb + (uint32_t)((buf * 128 * 36 + r * 36 + q * 4) * 4), sk);
            const float* sv = qkv + (long)(b * Nq + jt * 128 + r) * 768 + 512 + h * 32 + q * 4;
            CP_ASYNC16(vb + (uint32_t)((buf * 128 * 40 + r * 40 + q * 4) * 4), sv);
        }
        CP_COMMIT();
    };
    load_kv(0, 0);

    if (tid < 128) { m_run[tid] = -1e30f; l_run[tid] = 0.f; }
    float acc_o[4][4];
    #pragma unroll
    for (int nt = 0; nt < 4; nt++)
        #pragma unroll
        for (int q = 0; q < 4; q++) acc_o[nt][q] = 0.f;

    const float scq = 0.17677669529663689f;  // 1/sqrt(32)
    const uint32_t* Qu = (const uint32_t*)Qs;

    #pragma unroll 1
    for (int jt = 0; jt < 8; jt++) {
        int buf = jt & 1;
        if (jt < 7) load_kv(jt + 1, buf ^ 1);
        if (jt < 7) { CP_WAIT1(); } else { CP_WAIT0(); }
        __syncthreads();

        // ---- S = Q @ K^T ----
        float acc_s[4][4][4];
        #pragma unroll
        for (int mt = 0; mt < 4; mt++)
            #pragma unroll
            for (int nt = 0; nt < 4; nt++)
                #pragma unroll
                for (int q = 0; q < 4; q++) acc_s[mt][nt][q] = 0.f;

        const uint32_t* Ku = (const uint32_t*)(Ks + buf * 128 * 36);
        int mbase = wm * 64, nbw = wn * 32;
        #pragma unroll
        for (int s = 0; s < 4; s++) {
            int k = s * 8 + tig;
            uint32_t af[4][4];
            #pragma unroll
            for (int mt = 0; mt < 4; mt++) {
                const uint32_t* p = Qu + (mbase + mt * 16 + g) * 36 + k;
                af[mt][0] = p[0];  af[mt][1] = p[8 * 36];
                af[mt][2] = p[4];  af[mt][3] = p[8 * 36 + 4];
            }
            uint32_t bf[4][2];
            #pragma unroll
            for (int nt = 0; nt < 4; nt++) {
                const uint32_t* p = Ku + (nbw + nt * 8 + g) * 36 + k;
                bf[nt][0] = p[0]; bf[nt][1] = p[4];
            }
            #pragma unroll
            for (int mt = 0; mt < 4; mt++)
                #pragma unroll
                for (int nt = 0; nt < 4; nt++)
                    mma_tf32_16x8x8(acc_s[mt][nt], af[mt], bf[nt]);
        }
        #pragma unroll
        for (int nt = 0; nt < 4; nt++) {
            int col = nbw + nt * 8 + tig * 2;
            #pragma unroll
            for (int mt = 0; mt < 4; mt++) {
                int r = mbase + mt * 16 + g;
                *(float2*)(Ss + r * 132 + col) =
                    make_float2(acc_s[mt][nt][0] * scq, acc_s[mt][nt][1] * scq);
                *(float2*)(Ss + (r + 8) * 132 + col) =
                    make_float2(acc_s[mt][nt][2] * scq, acc_s[mt][nt][3] * scq);
            }
        }
        __syncthreads();

        // ---- online softmax stats (2 threads per row) ----
        {
            int r = tid >> 1, half = tid & 1;
            float* srow = Ss + r * 132 + half * 64;
            float mx = -1e30f;
            #pragma unroll 8
            for (int i = 0; i < 64; i++) mx = fmaxf(mx, srow[i]);
            mx = fmaxf(mx, __shfl_xor_sync(0xffffffffu, mx, 1));
            float m_old = m_run[r];
            float m_new = fmaxf(m_old, mx);
            float s = 0.f;
            #pragma unroll 8
            for (int i = 0; i < 64; i++) {
                float e = __expf(srow[i] - m_new);
                srow[i] = e;
                s += e;
            }
            s += __shfl_xor_sync(0xffffffffu, s, 1);
            if (!half) {
                float scl = __expf(m_old - m_new);
                sc_row[r] = scl;
                l_run[r] = l_run[r] * scl + s;
                m_run[r] = m_new;
            }
        }
        __syncthreads();

        // ---- O = O*scale + P @ V ----
        {
            float sc0 = sc_row[pvm + g];
            float sc1 = sc_row[pvm + g + 8];
            #pragma unroll
            for (int nt = 0; nt < 4; nt++) {
                acc_o[nt][0] *= sc0; acc_o[nt][1] *= sc0;
                acc_o[nt][2] *= sc1; acc_o[nt][3] *= sc1;
            }
            const uint32_t* Pu = (const uint32_t*)Ss;
            const uint32_t* Vu = (const uint32_t*)(Vs + buf * 128 * 40);
            #pragma unroll
            for (int s = 0; s < 16; s++) {
                int k0 = s * 8;
                uint32_t af[4];
                const uint32_t* p = Pu + (pvm + g) * 132 + k0 + tig;
                af[0] = p[0];        af[1] = p[8 * 132];
                af[2] = p[4];        af[3] = p[8 * 132 + 4];
                #pragma unroll
                for (int nt = 0; nt < 4; nt++) {
                    uint32_t bf[2];
                    const uint32_t* vp = Vu + (k0 + tig) * 40 + nt * 8 + g;
                    bf[0] = vp[0]; bf[1] = vp[4 * 40];
                    mma_tf32_16x8x8(acc_o[nt], af, bf);
                }
            }
        }
        __syncthreads();
    }

    float inv0 = 1.f / l_run[pvm + g];
    float inv1 = 1.f / l_run[pvm + g + 8];
    #pragma unroll
    for (int nt = 0; nt < 4; nt++) {
        int col = h * 32 + nt * 8 + tig * 2;
        long r = (long)b * Nq + i0 + pvm + g;
        *(float2*)(sa + r * 256 + col) =
            make_float2(acc_o[nt][0] * inv0, acc_o[nt][1] * inv0);
        *(float2*)(sa + (r + 8) * 256 + col) =
            make_float2(acc_o[nt][2] * inv1, acc_o[nt][3] * inv1);
    }
}

// ---------------- residual + LayerNorm (optional transposed in/out) ----------------
__global__ void add_ln_kernel(const float* __restrict__ x, int x_t,
                              const float* __restrict__ y,
                              const float* __restrict__ g, const float* __restrict__ be,
                              float* __restrict__ out, int out_t)
{
    int bn = blockIdx.x, b = bn >> 10, n = bn & 1023;
    int c = threadIdx.x;
    float xv = x_t ? x[(long)(b*256 + c)*Nq + n] : x[(long)bn*256 + c];
    float v = xv + y[(long)bn*256 + c];
    __shared__ float s1[8], s2[8];
    float a = v, q = v*v;
    #pragma unroll
    for (int o=16;o>0;o>>=1) { a += __shfl_xor_sync(0xffffffffu, a, o); q += __shfl_xor_sync(0xffffffffu, q, o); }
    if ((c & 31) == 0) { s1[c>>5] = a; s2[c>>5] = q; }
    __syncthreads();
    float sa_ = 0.f, sq = 0.f;
    #pragma unroll
    for (int w=0;w<8;w++) { sa_ += s1[w]; sq += s2[w]; }
    float mean = sa_*(1.f/256.f);
    float var  = sq*(1.f/256.f) - mean*mean;
    float inv  = rsqrtf(var + 1e-5f);
    float o = (v - mean)*inv*g[c] + be[c];
    if (out_t) out[(long)(b*256 + c)*Nq + n] = o;
    else       out[(long)bn*256 + c] = o;
}

// ---------------- residual + 4-partial reduce + bias + LayerNorm (FFN2 tail) ----------------
__global__ void add_ln4_kernel(const float* __restrict__ x,
                               const float* __restrict__ parts,
                               const float* __restrict__ bias,
                               const float* __restrict__ g, const float* __restrict__ be,
                               float* __restrict__ out)
{
    int bn = blockIdx.x, b = bn >> 10, n = bn & 1023;
    int c = threadIdx.x;
    const long stride = (long)Bq * Nq * 256;
    float v = x[(long)bn*256 + c] + bias[c];
    #pragma unroll
    for (int s = 0; s < 4; s++) v += parts[s * stride + (long)bn*256 + c];
    __shared__ float s1[8], s2[8];
    float a = v, q = v*v;
    #pragma unroll
    for (int o=16;o>0;o>>=1) { a += __shfl_xor_sync(0xffffffffu, a, o); q += __shfl_xor_sync(0xffffffffu, q, o); }
    if ((c & 31) == 0) { s1[c>>5] = a; s2[c>>5] = q; }
    __syncthreads();
    float sa_ = 0.f, sq = 0.f;
    #pragma unroll
    for (int w=0;w<8;w++) { sa_ += s1[w]; sq += s2[w]; }
    float mean = sa_*(1.f/256.f);
    float var  = sq*(1.f/256.f) - mean*mean;
    float inv  = rsqrtf(var + 1e-5f);
    float o = (v - mean)*inv*g[c] + be[c];
    out[(long)(b*256 + c)*Nq + n] = o;   // transposed final output
}

// ---------------- multi-scale deformable sampling (fp16 values) ----------------
__global__ void deform_kernel(const float* __restrict__ off, const float* __restrict__ awr,
                              const float* __restrict__ qpos, float* __restrict__ ca)
{
    int bn = blockIdx.x, b = bn >> 10;
    int tid = threadIdx.x;       // tid = h*32 + d
    int h = tid >> 5;
    __shared__ float s_off[192], s_aw[96];
    if (tid < 192) s_off[tid] = off[(long)bn*192 + tid];
    if (tid < 96)  s_aw[tid]  = awr[(long)bn*96 + tid];
    __syncthreads();

    float wl[12];
    {
        float mx = -1e30f;
        #pragma unroll
        for (int t=0;t<12;t++) mx = fmaxf(mx, s_aw[h*12+t]);
        float s = 0.f;
        #pragma unroll
        for (int t=0;t<12;t++) { wl[t] = __expf(s_aw[h*12+t]-mx); s += wl[t]; }
        float inv = 1.f/s;
        #pragma unroll
        for (int t=0;t<12;t++) wl[t] *= inv;
    }
    float rx = qpos[(long)bn*2+0] * (1.f/352.f);
    float ry = qpos[(long)bn*2+1] * (1.f/400.f);
    float acc = 0.f;
    #pragma unroll
    for (int l = 0; l < 3; l++) {
        const int Hh = (l < 2) ? 200 : 400;
        const int Ww = (l < 2) ? 176 : 352;
        const long base = ((l == 0) ? VOFF0 : (l == 1) ? VOFF1 : VOFF2)
                          + (long)b * Hh * Ww * 256 + tid;
        float fx = rx * (float)Ww, fy = ry * (float)Hh;
        #pragma unroll
        for (int p = 0; p < 4; p++) {
            int oi = (h*12 + l*4 + p)*2;
            float x = fx + s_off[oi]   - 0.5f;
            float y = fy + s_off[oi+1] - 0.5f;
            float x0f = floorf(x), y0f = floorf(y);
            float wx = x - x0f, wy = y - y0f;
            float aw = wl[l*4+p];
            float w00 = (1.f-wx)*(1.f-wy)*aw, w10 = wx*(1.f-wy)*aw;
            float w01 = (1.f-wx)*wy*aw,       w11 = wx*wy*aw;
            bool vx0 = (x0f >= 0.f)  & (x0f <  (float)Ww);
            bool vx1 = (x0f >= -1.f) & (x0f <  (float)(Ww-1));
            bool vy0 = (y0f >= 0.f)  & (y0f <  (float)Hh);
            bool vy1 = (y0f >= -1.f) & (y0f <  (float)(Hh-1));
            if (vx0 | vx1) {
                int ix0 = (int)x0f;
                if (vy0 | vy1) {
                    int iy0 = (int)y0f;
                    if (vx0 && vy0) acc += w00 * __half2float(g_values[base + (long)(iy0*Ww + ix0)*256]);
                    if (vx1 && vy0) acc += w10 * __half2float(g_values[base + (long)(iy0*Ww + ix0 + 1)*256]);
                    if (vx0 && vy1) acc += w01 * __half2float(g_values[base + (long)((iy0+1)*Ww + ix0)*256]);
                    if (vx1 && vy1) acc += w11 * __half2float(g_values[base + (long)((iy0+1)*Ww + ix0 + 1)*256]);
                }
            }
        }
    }
    ca[(long)bn*256 + tid] = acc;
}

// ---------------- launch (fork value stage || self-attn chain; join at deform) ----------------
extern "C" void kernel_launch(void* const* d_in, const int* in_sizes, int n_in,
                              void* d_out, int out_size)
{
    const float* query = (const float*)d_in[0];
    const float* qpos  = (const float*)d_in[1];
    const float* bev   = (const float*)d_in[2];
    const float* xc4   = (const float*)d_in[3];
    const float* xc3   = (const float*)d_in[4];
    const float* in_w  = (const float*)d_in[5];
    const float* in_b  = (const float*)d_in[6];
    const float* op_w  = (const float*)d_in[7];
    const float* op_b  = (const float*)d_in[8];
    const float* w_off = (const float*)d_in[9];
    const float* b_off = (const float*)d_in[10];
    const float* w_att = (const float*)d_in[11];
    const float* b_att = (const float*)d_in[12];
    const float* w_val = (const float*)d_in[13];
    const float* b_val = (const float*)d_in[14];
    const float* w_out = (const float*)d_in[15];
    const float* b_out = (const float*)d_in[16];
    const float* w_f1  = (const float*)d_in[17];
    const float* b_f1  = (const float*)d_in[18];
    const float* w_f2  = (const float*)d_in[19];
    const float* b_f2  = (const float*)d_in[20];
    const float* g1  = (const float*)d_in[21];
    const float* be1 = (const float*)d_in[22];
    const float* g2  = (const float*)d_in[23];
    const float* be2 = (const float*)d_in[24];
    const float* g3  = (const float*)d_in[25];
    const float* be3 = (const float*)d_in[26];
    float* out = (float*)d_out;
    (void)in_sizes; (void)n_in; (void)out_size;

    float *p_qkv, *p_sa, *p_tmp, *p_q1, *p_q2, *p_off, *p_aw, *p_ca, *p_ffh, *p_ffp;
    __half *p_val;
    cudaGetSymbolAddress((void**)&p_qkv, g_qkv);
    cudaGetSymbolAddress((void**)&p_sa,  g_sa);
    cudaGetSymbolAddress((void**)&p_tmp, g_tmp);
    cudaGetSymbolAddress((void**)&p_q1,  g_q1);
    cudaGetSymbolAddress((void**)&p_q2,  g_q2);
    cudaGetSymbolAddress((void**)&p_off, g_off);
    cudaGetSymbolAddress((void**)&p_aw,  g_aw);
    cudaGetSymbolAddress((void**)&p_ca,  g_ca);
    cudaGetSymbolAddress((void**)&p_val, g_values);
    cudaGetSymbolAddress((void**)&p_ffh, g_ffh);
    cudaGetSymbolAddress((void**)&p_ffp, g_ffp);

    cudaFuncSetAttribute(gemm_mma_at, cudaFuncAttributeMaxDynamicSharedMemorySize, AT_SMEM);
    cudaFuncSetAttribute(gemm_mma_a,  cudaFuncAttributeMaxDynamicSharedMemorySize, 4*GA_WORDS*4);
    cudaFuncSetAttribute(gemm_offaw,  cudaFuncAttributeMaxDynamicSharedMemorySize, 4*GA_WORDS*4);
    cudaFuncSetAttribute(ffn2_sk,     cudaFuncAttributeMaxDynamicSharedMemorySize, 4*GA_WORDS*4);
    cudaFuncSetAttribute(flash_attn,  cudaFuncAttributeMaxDynamicSharedMemorySize, FL_SMEM);

    // Side stream + events (created once; graph-capture fork/join pattern)
    static cudaStream_t s1 = [](){ cudaStream_t s; cudaStreamCreate(&s); return s; }();
    static cudaEvent_t ev0 = [](){ cudaEvent_t e; cudaEventCreateWithFlags(&e, cudaEventDisableTiming); return e; }();
    static cudaEvent_t ev1 = [](){ cudaEvent_t e; cudaEventCreateWithFlags(&e, cudaEventDisableTiming); return e; }();

    // ---- fork: value projections on s1 (independent of self-attn chain) ----
    cudaEventRecord(ev0, 0);
    cudaStreamWaitEvent(s1, ev0, 0);
    gemm_mma_at<<<dim3(HW2/128, 2, 2), 256, AT_SMEM, s1>>>(xc3, w_val, b_val, p_val + VOFF2, HW2, 256, 1);
    gemm_mma_at<<<dim3(HW0/128, 2, 2), 256, AT_SMEM, s1>>>(bev, w_val, b_val, p_val + VOFF0, HW0, 256, 1);
    gemm_mma_at<<<dim3(HW0/128, 2, 2), 256, AT_SMEM, s1>>>(xc4, w_val, b_val, p_val + VOFF1, HW0, 256, 1);
    cudaEventRecord(ev1, s1);

    // ---- self-attention chain on main stream (overlaps value stage) ----
    gemm_mma_at<<<dim3(8, 6, 2), 256, AT_SMEM>>>(query, in_w, in_b, p_qkv, 1024, 768, 0);
    flash_attn<<<dim3(8, 16), 256, FL_SMEM>>>(p_qkv, p_sa);
    gemm_mma_a<<<dim3(16, 2), 256, 4*GA_WORDS*4>>>(p_sa, op_w, op_b, p_tmp, 256, 256, 256, 256, 0);
    add_ln_kernel<<<2048, 256>>>(query, 1, p_tmp, g1, be1, p_q1, 0);
    gemm_offaw<<<dim3(16, 3), 256, 4*GA_WORDS*4>>>(p_q1, w_off, b_off, p_off, w_att, b_att, p_aw);

    // ---- join: deform needs the projected values ----
    cudaStreamWaitEvent(0, ev1, 0);
    deform_kernel<<<2048, 256>>>(p_off, p_aw, qpos, p_ca);
    gemm_mma_a<<<dim3(16, 2), 256, 4*GA_WORDS*4>>>(p_ca, w_out, b_out, p_tmp, 256, 256, 256, 256, 0);
    add_ln_kernel<<<2048, 256>>>(p_q1, 0, p_tmp, g2, be2, p_q2, 0);

    // ---- FFN ----
    gemm_mma_a<<<dim3(16, 16), 256, 4*GA_WORDS*4>>>(p_q2, w_f1, b_f1, p_ffh, 2048, 256, 256, 2048, 1);
    ffn2_sk<<<dim3(16, 2, 4), 256, 4*GA_WORDS*4>>>(p_ffh, w_f2, p_ffp);
    add_ln4_kernel<<<2048, 256>>>(p_q2, p_ffp, b_f2, g3, be3, out);
}